// round 1
// baseline (speedup 1.0000x reference)
#include <cuda_runtime.h>
#include <cuda_bf16.h>
#include <math.h>
#include <stdint.h>

// Problem constants
#define BB 4
#define MM 2048
#define DD 1024
#define HH 16
#define DH 64
#define RR 256
#define FD 2048
#define RR1 512
#define RR2 512
#define NN (BB*MM)   // 8192 tokens

// ---------------------------------------------------------------------------
// Scratch (device globals; allocation-free)
// ---------------------------------------------------------------------------
__device__ float g_XN [NN*DD];
__device__ float g_Pq [NN*RR];
__device__ float g_Pk [NN*RR];
__device__ float g_Pv [NN*RR];
__device__ float g_Qb [NN*DD];
__device__ float g_Kb [NN*DD];
__device__ float g_Vb [NN*DD];
__device__ float g_AO [NN*DD];
__device__ float g_XN2[NN*DD];
__device__ float g_P2 [NN*RR1];
__device__ float g_Hb [NN*2*FD];
__device__ float g_G  [NN*FD];
__device__ float g_T  [NN*RR2];
__device__ float g_ropeC[MM*32];
__device__ float g_ropeS[MM*32];

// ---------------------------------------------------------------------------
// LayerNorm: one block per row (D=1024), 256 threads, float4 per thread
// ---------------------------------------------------------------------------
__device__ __forceinline__ float block_sum(float v) {
    __shared__ float sh[8];
    int lane = threadIdx.x & 31, w = threadIdx.x >> 5;
    #pragma unroll
    for (int o = 16; o; o >>= 1) v += __shfl_xor_sync(0xffffffffu, v, o);
    __syncthreads();
    if (lane == 0) sh[w] = v;
    __syncthreads();
    float t = 0.f;
    #pragma unroll
    for (int i = 0; i < 8; i++) t += sh[i];
    return t;
}

__global__ __launch_bounds__(256) void ln_kernel(
    const float* __restrict__ x, const float* __restrict__ w,
    const float* __restrict__ b, float* __restrict__ out)
{
    size_t row = blockIdx.x;
    int t = threadIdx.x;
    float4 v = ((const float4*)(x + row*DD))[t];
    float mu = block_sum(v.x + v.y + v.z + v.w) * (1.f/1024.f);
    float dx = v.x - mu, dy = v.y - mu, dz = v.z - mu, dw = v.w - mu;
    float var = block_sum(dx*dx + dy*dy + dz*dz + dw*dw) * (1.f/1024.f);
    float rs = rsqrtf(var + 1e-5f);
    float4 wv = ((const float4*)w)[t];
    float4 bv = ((const float4*)b)[t];
    float4 o;
    o.x = dx*rs*wv.x + bv.x;
    o.y = dy*rs*wv.y + bv.y;
    o.z = dz*rs*wv.z + bv.z;
    o.w = dw*rs*wv.w + bv.w;
    ((float4*)(out + row*DD))[t] = o;
}

// ---------------------------------------------------------------------------
// SGEMM: C[Mrows,Nc] = A[Mrows,Kd] @ B (+bias)(+res)
// BT=false: B is [Kd,Nc] row-major.  BT=true: B is [Nc,Kd] row-major (B^T).
// 128x128 block tile, BK=8, 256 threads, 8x8 per thread. All dims multiples
// of tile sizes for this problem — no bounds checks.
// ---------------------------------------------------------------------------
template<bool BT, bool BIAS, bool RES>
__global__ __launch_bounds__(256) void sgemm(
    const float* __restrict__ A, const float* __restrict__ Bm,
    const float* __restrict__ bias, const float* __restrict__ res,
    float* __restrict__ C, int Nc, int Kd)
{
    __shared__ float As[8][128];
    __shared__ float Bs[8][128];
    int tid = threadIdx.x;
    int tx = tid & 15, ty = tid >> 4;
    int m0 = blockIdx.y << 7, n0 = blockIdx.x << 7;
    int am = tid >> 1, ak = (tid & 1) << 2;

    float acc[8][8];
    #pragma unroll
    for (int i = 0; i < 8; i++)
        #pragma unroll
        for (int j = 0; j < 8; j++) acc[i][j] = 0.f;

    for (int k0 = 0; k0 < Kd; k0 += 8) {
        float4 a4 = *(const float4*)&A[(size_t)(m0+am)*Kd + k0 + ak];
        As[ak+0][am] = a4.x; As[ak+1][am] = a4.y;
        As[ak+2][am] = a4.z; As[ak+3][am] = a4.w;
        if (BT) {
            int bn = tid >> 1, bk = (tid & 1) << 2;
            float4 b4 = *(const float4*)&Bm[(size_t)(n0+bn)*Kd + k0 + bk];
            Bs[bk+0][bn] = b4.x; Bs[bk+1][bn] = b4.y;
            Bs[bk+2][bn] = b4.z; Bs[bk+3][bn] = b4.w;
        } else {
            int bk = tid >> 5, bn4 = (tid & 31) << 2;
            *(float4*)&Bs[bk][bn4] =
                *(const float4*)&Bm[(size_t)(k0+bk)*Nc + n0 + bn4];
        }
        __syncthreads();
        #pragma unroll
        for (int kk = 0; kk < 8; kk++) {
            float a[8], bfr[8];
            *(float4*)(a)     = *(const float4*)&As[kk][ty*8];
            *(float4*)(a+4)   = *(const float4*)&As[kk][ty*8+4];
            *(float4*)(bfr)   = *(const float4*)&Bs[kk][tx*8];
            *(float4*)(bfr+4) = *(const float4*)&Bs[kk][tx*8+4];
            #pragma unroll
            for (int i = 0; i < 8; i++)
                #pragma unroll
                for (int j = 0; j < 8; j++)
                    acc[i][j] += a[i]*bfr[j];
        }
        __syncthreads();
    }

    #pragma unroll
    for (int i = 0; i < 8; i++) {
        size_t gm = (size_t)(m0 + ty*8 + i);
        #pragma unroll
        for (int j = 0; j < 8; j += 4) {
            int gn = n0 + tx*8 + j;
            float4 v = make_float4(acc[i][j], acc[i][j+1], acc[i][j+2], acc[i][j+3]);
            if (BIAS) {
                float4 bb = *(const float4*)&bias[gn];
                v.x += bb.x; v.y += bb.y; v.z += bb.z; v.w += bb.w;
            }
            if (RES) {
                float4 r = *(const float4*)&res[gm*Nc + gn];
                v.x += r.x; v.y += r.y; v.z += r.z; v.w += r.w;
            }
            *(float4*)&C[gm*Nc + gn] = v;
        }
    }
}

// ---------------------------------------------------------------------------
// RoPE table (double-precision trig of the fp32 angle, matching JAX fp32 ref)
// ---------------------------------------------------------------------------
__global__ void rope_table_kernel() {
    int idx = blockIdx.x*256 + threadIdx.x;   // 65536 = 2048*32
    int m = idx >> 5, i = idx & 31;
    double e = (double)(2*i) / 64.0;
    float invf = (float)(1.0 / pow(10000.0, e));
    float ang = (float)m * invf;
    double a = (double)ang;
    g_ropeC[idx] = (float)cos(a);
    g_ropeS[idx] = (float)sin(a);
}

// Apply RoPE in place to Q and K ([N, D] token-major, heads packed in cols)
__global__ __launch_bounds__(256) void rope_kernel(
    float* __restrict__ Q, float* __restrict__ K)
{
    int idx = blockIdx.x*256 + threadIdx.x;   // N*H*32 = 4194304
    int n = idx >> 9;
    int r = idx & 511;
    int h = r >> 5, i = r & 31;
    int m = n & (MM - 1);
    float c = g_ropeC[m*32 + i];
    float s = g_ropeS[m*32 + i];
    size_t base = (size_t)n*DD + h*DH + i;
    float a1 = Q[base], a2 = Q[base + 32];
    Q[base]      = a1*c - a2*s;
    Q[base + 32] = a2*c + a1*s;
    float b1 = K[base], b2 = K[base + 32];
    K[base]      = b1*c - b2*s;
    K[base + 32] = b2*c + b1*s;
}

// ---------------------------------------------------------------------------
// Flash attention, fp32. Block = 64 query rows x one (b,h). 256 threads
// (16x16), each owns a 4(row) x 4 tile for S and for O. Online softmax with
// width-16 shuffle reductions. Smem: Qt/Kt (d-major, transposed), Vs
// (kv-major), Pt (kv-major) — stride 68 floats, 69632 B dynamic smem.
// ---------------------------------------------------------------------------
#define FA_STR 68
#define FA_SMEM (4*64*FA_STR*4)

__global__ __launch_bounds__(256) void fa_kernel(
    const float* __restrict__ Q, const float* __restrict__ K,
    const float* __restrict__ V, const int* __restrict__ mask,
    float* __restrict__ O)
{
    extern __shared__ float sm[];
    float* Qt = sm;                 // [64 d][68]
    float* Kt = sm + 64*FA_STR;     // [64 d][68]
    float* Vs = sm + 2*64*FA_STR;   // [64 kv][68 dh]
    float* Pt = sm + 3*64*FA_STR;   // [64 kv][68 qi]

    int tid = threadIdx.x, tx = tid & 15, ty = tid >> 4;
    int m0 = blockIdx.x * 64;
    int b = blockIdx.y >> 4, h = blockIdx.y & 15;
    size_t qbase = ((size_t)(b*MM + m0))*DD + h*DH;

    #pragma unroll
    for (int it = 0; it < 4; it++) {
        int idx = tid + it*256;
        int row = idx >> 4, d4 = (idx & 15) << 2;
        float4 q = *(const float4*)&Q[qbase + (size_t)row*DD + d4];
        Qt[(d4+0)*FA_STR + row] = q.x;
        Qt[(d4+1)*FA_STR + row] = q.y;
        Qt[(d4+2)*FA_STR + row] = q.z;
        Qt[(d4+3)*FA_STR + row] = q.w;
    }

    float mrow[4], lrow[4], o[4][4];
    #pragma unroll
    for (int r = 0; r < 4; r++) {
        mrow[r] = -1e30f; lrow[r] = 0.f;
        #pragma unroll
        for (int c = 0; c < 4; c++) o[r][c] = 0.f;
    }
    const int* mb = mask + b*MM;

    for (int t = 0; t < MM/64; t++) {
        int j0 = t*64;
        __syncthreads();
        size_t kb = ((size_t)(b*MM + j0))*DD + h*DH;
        #pragma unroll
        for (int it = 0; it < 4; it++) {
            int idx = tid + it*256;
            int row = idx >> 4, d4 = (idx & 15) << 2;
            float4 kv = *(const float4*)&K[kb + (size_t)row*DD + d4];
            Kt[(d4+0)*FA_STR + row] = kv.x;
            Kt[(d4+1)*FA_STR + row] = kv.y;
            Kt[(d4+2)*FA_STR + row] = kv.z;
            Kt[(d4+3)*FA_STR + row] = kv.w;
            float4 vv = *(const float4*)&V[kb + (size_t)row*DD + d4];
            *(float4*)&Vs[row*FA_STR + d4] = vv;
        }
        __syncthreads();

        float s_[4][4];
        #pragma unroll
        for (int r = 0; r < 4; r++)
            #pragma unroll
            for (int c = 0; c < 4; c++) s_[r][c] = 0.f;

        #pragma unroll 8
        for (int d = 0; d < 64; d++) {
            float a[4], bk_[4];
            *(float4*)a   = *(const float4*)&Qt[d*FA_STR + ty*4];
            *(float4*)bk_ = *(const float4*)&Kt[d*FA_STR + tx*4];
            #pragma unroll
            for (int r = 0; r < 4; r++)
                #pragma unroll
                for (int c = 0; c < 4; c++)
                    s_[r][c] += a[r]*bk_[c];
        }

        int mk[4];
        #pragma unroll
        for (int c = 0; c < 4; c++) mk[c] = mb[j0 + tx*4 + c];

        #pragma unroll
        for (int r = 0; r < 4; r++) {
            float mx = -1e30f;
            #pragma unroll
            for (int c = 0; c < 4; c++) {
                float v = s_[r][c] * 0.125f;     // 1/sqrt(64)
                if (mk[c] == 0) v = -1e30f;
                s_[r][c] = v;
                mx = fmaxf(mx, v);
            }
            #pragma unroll
            for (int off = 8; off; off >>= 1)
                mx = fmaxf(mx, __shfl_xor_sync(0xffffffffu, mx, off, 16));
            float mn = fmaxf(mrow[r], mx);
            float corr = __expf(mrow[r] - mn);
            float ps = 0.f;
            #pragma unroll
            for (int c = 0; c < 4; c++) {
                float p = __expf(s_[r][c] - mn);
                s_[r][c] = p;
                ps += p;
            }
            #pragma unroll
            for (int off = 8; off; off >>= 1)
                ps += __shfl_xor_sync(0xffffffffu, ps, off, 16);
            lrow[r] = lrow[r]*corr + ps;
            mrow[r] = mn;
            #pragma unroll
            for (int c = 0; c < 4; c++) o[r][c] *= corr;
        }

        #pragma unroll
        for (int c = 0; c < 4; c++)
            *(float4*)&Pt[(tx*4 + c)*FA_STR + ty*4] =
                make_float4(s_[0][c], s_[1][c], s_[2][c], s_[3][c]);
        __syncthreads();

        #pragma unroll 8
        for (int k = 0; k < 64; k++) {
            float a[4], vv[4];
            *(float4*)a  = *(const float4*)&Pt[k*FA_STR + ty*4];
            *(float4*)vv = *(const float4*)&Vs[k*FA_STR + tx*4];
            #pragma unroll
            for (int r = 0; r < 4; r++)
                #pragma unroll
                for (int c = 0; c < 4; c++)
                    o[r][c] += a[r]*vv[c];
        }
    }

    #pragma unroll
    for (int r = 0; r < 4; r++) {
        float inv = 1.f / lrow[r];
        size_t orow = ((size_t)(b*MM + m0 + ty*4 + r))*DD + h*DH + tx*4;
        *(float4*)&O[orow] =
            make_float4(o[r][0]*inv, o[r][1]*inv, o[r][2]*inv, o[r][3]*inv);
    }
}

// ---------------------------------------------------------------------------
// GEGLU: g = gelu_tanh(h[:, :FD]) * h[:, FD:2FD]
// ---------------------------------------------------------------------------
__device__ __forceinline__ float gelu_t(float x) {
    float x3 = x*x*x;
    return 0.5f * x * (1.f + tanhf(0.7978845608028654f * (x + 0.044715f*x3)));
}

__global__ __launch_bounds__(256) void geglu_kernel(
    const float* __restrict__ h, float* __restrict__ g)
{
    size_t i = (size_t)blockIdx.x*256 + threadIdx.x;  // over N * FD/4 = 4194304
    size_t n = i >> 9;        // FD/4 = 512 float4 per row
    size_t f4 = i & 511;
    float4 a  = *(const float4*)&h[n*(2*FD) + f4*4];
    float4 c2 = *(const float4*)&h[n*(2*FD) + FD + f4*4];
    float4 o;
    o.x = gelu_t(a.x) * c2.x;
    o.y = gelu_t(a.y) * c2.y;
    o.z = gelu_t(a.z) * c2.z;
    o.w = gelu_t(a.w) * c2.w;
    *(float4*)&g[n*FD + f4*4] = o;
}

// ---------------------------------------------------------------------------
// Host launcher
// ---------------------------------------------------------------------------
extern "C" void kernel_launch(void* const* d_in, const int* in_sizes, int n_in,
                              void* d_out, int out_size)
{
    const float* x    = (const float*)d_in[0];
    const int*   mask = (const int*)  d_in[1];
    const float* ln1w = (const float*)d_in[2];
    const float* ln1b = (const float*)d_in[3];
    const float* ln2w = (const float*)d_in[4];
    const float* ln2b = (const float*)d_in[5];
    const float* Uq   = (const float*)d_in[6];
    const float* Uk   = (const float*)d_in[7];
    const float* Uv   = (const float*)d_in[8];
    const float* Vq   = (const float*)d_in[9];
    const float* Vk   = (const float*)d_in[10];
    const float* Vv   = (const float*)d_in[11];
    const float* bq   = (const float*)d_in[12];
    const float* bk   = (const float*)d_in[13];
    const float* bv   = (const float*)d_in[14];
    const float* Wo   = (const float*)d_in[15];
    const float* Wob  = (const float*)d_in[16];
    const float* U1   = (const float*)d_in[17];
    const float* V1   = (const float*)d_in[18];
    const float* b1   = (const float*)d_in[19];
    const float* U2   = (const float*)d_in[20];
    const float* V2   = (const float*)d_in[21];
    const float* b2   = (const float*)d_in[22];
    float* out = (float*)d_out;

    void* p;
    #define SYM(var, sym) cudaGetSymbolAddress(&p, sym); float* var = (float*)p;
    SYM(XN,  g_XN);  SYM(Pq_, g_Pq); SYM(Pk_, g_Pk); SYM(Pv_, g_Pv);
    SYM(Qb,  g_Qb);  SYM(Kb,  g_Kb); SYM(Vb,  g_Vb); SYM(AO,  g_AO);
    SYM(XN2, g_XN2); SYM(P2,  g_P2); SYM(Hb,  g_Hb); SYM(G,   g_G);
    SYM(T,   g_T);
    #undef SYM

    cudaFuncSetAttribute(fa_kernel,
        cudaFuncAttributeMaxDynamicSharedMemorySize, FA_SMEM);

    // RoPE tables (cheap; recomputed each call for determinism)
    rope_table_kernel<<<256, 256>>>();

    // LN1
    ln_kernel<<<NN, 256>>>(x, ln1w, ln1b, XN);

    // Rank projections: [N,1024] @ [1024,256]
    sgemm<false,false,false><<<dim3(RR/128, NN/128), 256>>>(XN, Uq, nullptr, nullptr, Pq_, RR, DD);
    sgemm<false,false,false><<<dim3(RR/128, NN/128), 256>>>(XN, Uk, nullptr, nullptr, Pk_, RR, DD);
    sgemm<false,false,false><<<dim3(RR/128, NN/128), 256>>>(XN, Uv, nullptr, nullptr, Pv_, RR, DD);

    // Expand + bias: [N,256] @ [256,1024]
    sgemm<false,true,false><<<dim3(DD/128, NN/128), 256>>>(Pq_, Vq, bq, nullptr, Qb, DD, RR);
    sgemm<false,true,false><<<dim3(DD/128, NN/128), 256>>>(Pk_, Vk, bk, nullptr, Kb, DD, RR);
    sgemm<false,true,false><<<dim3(DD/128, NN/128), 256>>>(Pv_, Vv, bv, nullptr, Vb, DD, RR);

    // RoPE on Q, K
    rope_kernel<<<(NN*HH*32)/256, 256>>>(Qb, Kb);

    // Attention
    fa_kernel<<<dim3(MM/64, BB*HH), 256, FA_SMEM>>>(Qb, Kb, Vb, mask, AO);

    // Out-proj (B^T) + bias + residual -> d_out holds x after attention
    sgemm<true,true,true><<<dim3(DD/128, NN/128), 256>>>(AO, Wo, Wob, x, out, DD, DD);

    // LN2
    ln_kernel<<<NN, 256>>>(out, ln2w, ln2b, XN2);

    // FFN rank path
    sgemm<false,false,false><<<dim3(RR1/128, NN/128), 256>>>(XN2, U1, nullptr, nullptr, P2, RR1, DD);
    sgemm<false,true,false><<<dim3((2*FD)/128, NN/128), 256>>>(P2, V1, b1, nullptr, Hb, 2*FD, RR1);
    geglu_kernel<<<(NN*(FD/4))/256, 256>>>(Hb, G);
    sgemm<false,false,false><<<dim3(RR2/128, NN/128), 256>>>(G, U2, nullptr, nullptr, T, RR2, FD);

    // Final: out = out(residual) + T @ V2 + b2  (in-place residual is safe:
    // each element read once then written once by the same thread)
    sgemm<false,true,true><<<dim3(DD/128, NN/128), 256>>>(T, V2, b2, out, out, DD, RR2);
}

// round 3
// speedup vs baseline: 2.0260x; 2.0260x over previous
#include <cuda_runtime.h>
#include <cuda_bf16.h>
#include <math.h>
#include <stdint.h>

// Problem constants
#define BB 4
#define MM 2048
#define DD 1024
#define HH 16
#define DH 64
#define RR 256
#define FD 2048
#define RR1 512
#define RR2 512
#define NN (BB*MM)   // 8192 tokens

typedef __nv_bfloat16 bf16;
typedef __nv_bfloat162 bf162;

// ---------------------------------------------------------------------------
// Scratch (device globals; allocation-free)
// ---------------------------------------------------------------------------
// bf16 activations
__device__ bf16 g_bXN [NN*DD];
__device__ bf16 g_bPq [NN*RR];
__device__ bf16 g_bPk [NN*RR];
__device__ bf16 g_bPv [NN*RR];
__device__ bf16 g_bAO [NN*DD];
__device__ bf16 g_bXN2[NN*DD];
__device__ bf16 g_bP2 [NN*RR1];
__device__ bf16 g_bHb [NN*2*FD];
__device__ bf16 g_bG  [NN*FD];
__device__ bf16 g_bT  [NN*RR2];
// bf16 weights
__device__ bf16 g_wUq [DD*RR];
__device__ bf16 g_wUk [DD*RR];
__device__ bf16 g_wUv [DD*RR];
__device__ bf16 g_wVq [RR*DD];
__device__ bf16 g_wVk [RR*DD];
__device__ bf16 g_wVv [RR*DD];
__device__ bf16 g_wWoT[DD*DD];
__device__ bf16 g_wU1 [DD*RR1];
__device__ bf16 g_wV1 [RR1*2*FD];
__device__ bf16 g_wU2 [FD*RR2];
__device__ bf16 g_wV2 [RR2*DD];
// fp32 (attention operands stay fp32 this round)
__device__ float g_Qb [NN*DD];
__device__ float g_Kb [NN*DD];
__device__ float g_Vb [NN*DD];
__device__ float g_ropeC[MM*32];
__device__ float g_ropeS[MM*32];

// ---------------------------------------------------------------------------
// Small PTX helpers
// ---------------------------------------------------------------------------
__device__ __forceinline__ void cp16(uint32_t dst, const void* src) {
    asm volatile("cp.async.cg.shared.global [%0], [%1], 16;\n" :: "r"(dst), "l"(src));
}
__device__ __forceinline__ void cp_commit() {
    asm volatile("cp.async.commit_group;\n" ::: "memory");
}
__device__ __forceinline__ void ldsm4(uint32_t* r, uint32_t addr) {
    asm volatile("ldmatrix.sync.aligned.m8n8.x4.shared.b16 {%0,%1,%2,%3}, [%4];\n"
        : "=r"(r[0]), "=r"(r[1]), "=r"(r[2]), "=r"(r[3]) : "r"(addr));
}
__device__ __forceinline__ void ldsm4t(uint32_t* r, uint32_t addr) {
    asm volatile("ldmatrix.sync.aligned.m8n8.x4.trans.shared.b16 {%0,%1,%2,%3}, [%4];\n"
        : "=r"(r[0]), "=r"(r[1]), "=r"(r[2]), "=r"(r[3]) : "r"(addr));
}
__device__ __forceinline__ void mma_bf16(float* c, const uint32_t* a, uint32_t b0, uint32_t b1) {
    asm volatile(
        "mma.sync.aligned.m16n8k16.row.col.f32.bf16.bf16.f32 "
        "{%0,%1,%2,%3}, {%4,%5,%6,%7}, {%8,%9}, {%0,%1,%2,%3};\n"
        : "+f"(c[0]), "+f"(c[1]), "+f"(c[2]), "+f"(c[3])
        : "r"(a[0]), "r"(a[1]), "r"(a[2]), "r"(a[3]), "r"(b0), "r"(b1));
}

// ---------------------------------------------------------------------------
// bf16 tensor-core GEMM: C[M,Nc] = A[M,Kd] @ B[Kd,Nc] (+bias)(+fp32 res)
// 128x128x64 block tile, 256 threads (8 warps as 4x2, warp tile 32x64),
// cp.async double buffer, XOR-swizzled smem, ldmatrix, m16n8k16.
// All dims are multiples of tile sizes here -> no bounds checks.
// ---------------------------------------------------------------------------
template<bool BIAS, bool RES, bool F32OUT>
__global__ __launch_bounds__(256, 2) void hgemm(
    const bf16* __restrict__ A, const bf16* __restrict__ B,
    const float* __restrict__ bias, const float* __restrict__ res,
    void* __restrict__ Cout, int Nc, int Kd)
{
    extern __shared__ bf16 smraw[];
    bf16* As = smraw;              // [2][128*64]
    bf16* Bs = smraw + 2*8192;     // [2][64*128]
    const int tid = threadIdx.x, lane = tid & 31, wid = tid >> 5;
    const int wm = (wid & 3) << 5;          // warp row offset (0..96)
    const int wn = (wid >> 2) << 6;         // warp col offset (0 or 64)
    const int m0 = blockIdx.y << 7, n0 = blockIdx.x << 7;
    const int KT = Kd >> 6;

    const uint32_t sA = (uint32_t)__cvta_generic_to_shared(As);
    const uint32_t sB = (uint32_t)__cvta_generic_to_shared(Bs);

    float acc[2][8][4];
    #pragma unroll
    for (int i = 0; i < 2; i++)
        #pragma unroll
        for (int j = 0; j < 8; j++)
            #pragma unroll
            for (int k = 0; k < 4; k++) acc[i][j][k] = 0.f;

    auto issue = [&](int kt, int buf) {
        const int k0 = kt << 6;
        const uint32_t da = sA + buf * 16384;
        #pragma unroll
        for (int t = 0; t < 4; t++) {
            int j = tid + (t << 8);
            int r = j >> 3, c = j & 7;
            const bf16* src = A + (size_t)(m0 + r) * Kd + k0 + (c << 3);
            uint32_t dst = da + (((r << 6) + ((c ^ (r & 7)) << 3)) << 1);
            cp16(dst, src);
        }
        const uint32_t db = sB + buf * 16384;
        #pragma unroll
        for (int t = 0; t < 4; t++) {
            int j = tid + (t << 8);
            int r = j >> 4, c = j & 15;
            int swc = (c & 8) | ((c & 7) ^ (r & 7));
            const bf16* src = B + (size_t)(k0 + r) * Nc + n0 + (c << 3);
            uint32_t dst = db + (((r << 7) + (swc << 3)) << 1);
            cp16(dst, src);
        }
    };

    issue(0, 0);
    cp_commit();

    int buf = 0;
    for (int kt = 0; kt < KT; kt++) {
        if (kt + 1 < KT) {
            issue(kt + 1, buf ^ 1);
            cp_commit();
            asm volatile("cp.async.wait_group 1;\n" ::: "memory");
        } else {
            asm volatile("cp.async.wait_group 0;\n" ::: "memory");
        }
        __syncthreads();

        const uint32_t aBase = sA + buf * 16384;
        const uint32_t bBase = sB + buf * 16384;
        #pragma unroll
        for (int ks = 0; ks < 4; ks++) {
            uint32_t afr[2][4];
            #pragma unroll
            for (int mt = 0; mt < 2; mt++) {
                int row = wm + mt * 16 + (lane & 15);
                int ch = 2 * ks + (lane >> 4);
                uint32_t addr = aBase + (((row << 6) + ((ch ^ (row & 7)) << 3)) << 1);
                ldsm4(afr[mt], addr);
            }
            uint32_t bfr[4][4];
            #pragma unroll
            for (int nt = 0; nt < 4; nt++) {
                int k = ks * 16 + (lane & 15);
                int ch = (wn >> 3) + nt * 2 + (lane >> 4);
                int swc = (ch & 8) | ((ch & 7) ^ (k & 7));
                uint32_t addr = bBase + (((k << 7) + (swc << 3)) << 1);
                ldsm4t(bfr[nt], addr);
            }
            #pragma unroll
            for (int mt = 0; mt < 2; mt++)
                #pragma unroll
                for (int nt = 0; nt < 4; nt++) {
                    mma_bf16(acc[mt][nt*2+0], afr[mt], bfr[nt][0], bfr[nt][1]);
                    mma_bf16(acc[mt][nt*2+1], afr[mt], bfr[nt][2], bfr[nt][3]);
                }
        }
        __syncthreads();
        buf ^= 1;
    }

    // Epilogue
    const int g = lane >> 2, q = (lane & 3) << 1;
    #pragma unroll
    for (int mt = 0; mt < 2; mt++)
        #pragma unroll
        for (int n8 = 0; n8 < 8; n8++) {
            int n = n0 + wn + n8 * 8 + q;
            float b0 = 0.f, b1 = 0.f;
            if (BIAS) { b0 = bias[n]; b1 = bias[n + 1]; }
            #pragma unroll
            for (int hh = 0; hh < 2; hh++) {
                int m = m0 + wm + mt * 16 + g + hh * 8;
                float v0 = acc[mt][n8][hh*2+0] + b0;
                float v1 = acc[mt][n8][hh*2+1] + b1;
                size_t off = (size_t)m * Nc + n;
                if (RES) {
                    const float* rp = res + off;
                    v0 += rp[0]; v1 += rp[1];
                }
                if (F32OUT) {
                    float* C = (float*)Cout;
                    C[off] = v0; C[off + 1] = v1;
                } else {
                    bf162* C = (bf162*)Cout;
                    C[off >> 1] = __floats2bfloat162_rn(v0, v1);
                }
            }
        }
}

// ---------------------------------------------------------------------------
// Weight conversion fp32 -> bf16
// ---------------------------------------------------------------------------
__global__ __launch_bounds__(256) void f2b_kernel(
    const float* __restrict__ s, bf16* __restrict__ d)
{
    int i = blockIdx.x * 256 + threadIdx.x;   // one float4 per thread
    float4 v = ((const float4*)s)[i];
    ((bf162*)d)[i*2+0] = __floats2bfloat162_rn(v.x, v.y);
    ((bf162*)d)[i*2+1] = __floats2bfloat162_rn(v.z, v.w);
}

// Transpose-convert: src fp32 [1024 out][1024 in] -> dst bf16 [in][out]
__global__ __launch_bounds__(256) void transb_kernel(
    const float* __restrict__ s, bf16* __restrict__ d)
{
    __shared__ float tile[32][33];
    int bx = blockIdx.x * 32;   // in-dim base
    int by = blockIdx.y * 32;   // out-dim base
    int tx = threadIdx.x & 31, ty = threadIdx.x >> 5;
    #pragma unroll
    for (int i = 0; i < 4; i++) {
        int row = by + ty + i * 8;
        tile[ty + i * 8][tx] = s[(size_t)row * DD + bx + tx];
    }
    __syncthreads();
    #pragma unroll
    for (int i = 0; i < 4; i++) {
        int orow = bx + ty + i * 8;
        d[(size_t)orow * DD + by + tx] = __float2bfloat16(tile[tx][ty + i * 8]);
    }
}

// ---------------------------------------------------------------------------
// LayerNorm: one block per row (D=1024), 256 threads, writes bf16
// ---------------------------------------------------------------------------
__device__ __forceinline__ float block_sum(float v) {
    __shared__ float sh[8];
    int lane = threadIdx.x & 31, w = threadIdx.x >> 5;
    #pragma unroll
    for (int o = 16; o; o >>= 1) v += __shfl_xor_sync(0xffffffffu, v, o);
    __syncthreads();
    if (lane == 0) sh[w] = v;
    __syncthreads();
    float t = 0.f;
    #pragma unroll
    for (int i = 0; i < 8; i++) t += sh[i];
    return t;
}

__global__ __launch_bounds__(256) void ln_kernel(
    const float* __restrict__ x, const float* __restrict__ w,
    const float* __restrict__ b, bf16* __restrict__ out)
{
    size_t row = blockIdx.x;
    int t = threadIdx.x;
    float4 v = ((const float4*)(x + row*DD))[t];
    float mu = block_sum(v.x + v.y + v.z + v.w) * (1.f/1024.f);
    float dx = v.x - mu, dy = v.y - mu, dz = v.z - mu, dw = v.w - mu;
    float var = block_sum(dx*dx + dy*dy + dz*dz + dw*dw) * (1.f/1024.f);
    float rs = rsqrtf(var + 1e-5f);
    float4 wv = ((const float4*)w)[t];
    float4 bv = ((const float4*)b)[t];
    bf162* o2 = (bf162*)(out + row*DD);
    o2[t*2+0] = __floats2bfloat162_rn(dx*rs*wv.x + bv.x, dy*rs*wv.y + bv.y);
    o2[t*2+1] = __floats2bfloat162_rn(dz*rs*wv.z + bv.z, dw*rs*wv.w + bv.w);
}

// ---------------------------------------------------------------------------
// RoPE
// ---------------------------------------------------------------------------
__global__ void rope_table_kernel() {
    int idx = blockIdx.x*256 + threadIdx.x;   // 65536 = 2048*32
    int m = idx >> 5, i = idx & 31;
    double e = (double)(2*i) / 64.0;
    float invf = (float)(1.0 / pow(10000.0, e));
    float ang = (float)m * invf;
    double a = (double)ang;
    g_ropeC[idx] = (float)cos(a);
    g_ropeS[idx] = (float)sin(a);
}

__global__ __launch_bounds__(256) void rope_kernel(
    float* __restrict__ Q, float* __restrict__ K)
{
    int idx = blockIdx.x*256 + threadIdx.x;   // N*H*32 = 4194304
    int n = idx >> 9;
    int r = idx & 511;
    int h = r >> 5, i = r & 31;
    int m = n & (MM - 1);
    float c = g_ropeC[m*32 + i];
    float s = g_ropeS[m*32 + i];
    size_t base = (size_t)n*DD + h*DH + i;
    float a1 = Q[base], a2 = Q[base + 32];
    Q[base]      = a1*c - a2*s;
    Q[base + 32] = a2*c + a1*s;
    float b1 = K[base], b2 = K[base + 32];
    K[base]      = b1*c - b2*s;
    K[base + 32] = b2*c + b1*s;
}

// ---------------------------------------------------------------------------
// Flash attention, fp32 compute, bf16 output. 64 query rows x one (b,h).
// ---------------------------------------------------------------------------
#define FA_STR 68
#define FA_SMEM (4*64*FA_STR*4)

__global__ __launch_bounds__(256) void fa_kernel(
    const float* __restrict__ Q, const float* __restrict__ K,
    const float* __restrict__ V, const int* __restrict__ mask,
    bf16* __restrict__ O)
{
    extern __shared__ float sm[];
    float* Qt = sm;                 // [64 d][68]
    float* Kt = sm + 64*FA_STR;     // [64 d][68]
    float* Vs = sm + 2*64*FA_STR;   // [64 kv][68 dh]
    float* Pt = sm + 3*64*FA_STR;   // [64 kv][68 qi]

    int tid = threadIdx.x, tx = tid & 15, ty = tid >> 4;
    int m0 = blockIdx.x * 64;
    int b = blockIdx.y >> 4, h = blockIdx.y & 15;
    size_t qbase = ((size_t)(b*MM + m0))*DD + h*DH;

    #pragma unroll
    for (int it = 0; it < 4; it++) {
        int idx = tid + it*256;
        int row = idx >> 4, d4 = (idx & 15) << 2;
        float4 q = *(const float4*)&Q[qbase + (size_t)row*DD + d4];
        Qt[(d4+0)*FA_STR + row] = q.x;
        Qt[(d4+1)*FA_STR + row] = q.y;
        Qt[(d4+2)*FA_STR + row] = q.z;
        Qt[(d4+3)*FA_STR + row] = q.w;
    }

    float mrow[4], lrow[4], o[4][4];
    #pragma unroll
    for (int r = 0; r < 4; r++) {
        mrow[r] = -1e30f; lrow[r] = 0.f;
        #pragma unroll
        for (int c = 0; c < 4; c++) o[r][c] = 0.f;
    }
    const int* mb = mask + b*MM;

    for (int t = 0; t < MM/64; t++) {
        int j0 = t*64;
        __syncthreads();
        size_t kb = ((size_t)(b*MM + j0))*DD + h*DH;
        #pragma unroll
        for (int it = 0; it < 4; it++) {
            int idx = tid + it*256;
            int row = idx >> 4, d4 = (idx & 15) << 2;
            float4 kv = *(const float4*)&K[kb + (size_t)row*DD + d4];
            Kt[(d4+0)*FA_STR + row] = kv.x;
            Kt[(d4+1)*FA_STR + row] = kv.y;
            Kt[(d4+2)*FA_STR + row] = kv.z;
            Kt[(d4+3)*FA_STR + row] = kv.w;
            float4 vv = *(const float4*)&V[kb + (size_t)row*DD + d4];
            *(float4*)&Vs[row*FA_STR + d4] = vv;
        }
        __syncthreads();

        float s_[4][4];
        #pragma unroll
        for (int r = 0; r < 4; r++)
            #pragma unroll
            for (int c = 0; c < 4; c++) s_[r][c] = 0.f;

        #pragma unroll 8
        for (int d = 0; d < 64; d++) {
            float a[4], bk_[4];
            *(float4*)a   = *(const float4*)&Qt[d*FA_STR + ty*4];
            *(float4*)bk_ = *(const float4*)&Kt[d*FA_STR + tx*4];
            #pragma unroll
            for (int r = 0; r < 4; r++)
                #pragma unroll
                for (int c = 0; c < 4; c++)
                    s_[r][c] += a[r]*bk_[c];
        }

        int mk[4];
        #pragma unroll
        for (int c = 0; c < 4; c++) mk[c] = mb[j0 + tx*4 + c];

        #pragma unroll
        for (int r = 0; r < 4; r++) {
            float mx = -1e30f;
            #pragma unroll
            for (int c = 0; c < 4; c++) {
                float v = s_[r][c] * 0.125f;
                if (mk[c] == 0) v = -1e30f;
                s_[r][c] = v;
                mx = fmaxf(mx, v);
            }
            #pragma unroll
            for (int off = 8; off; off >>= 1)
                mx = fmaxf(mx, __shfl_xor_sync(0xffffffffu, mx, off, 16));
            float mn = fmaxf(mrow[r], mx);
            float corr = __expf(mrow[r] - mn);
            float ps = 0.f;
            #pragma unroll
            for (int c = 0; c < 4; c++) {
                float p = __expf(s_[r][c] - mn);
                s_[r][c] = p;
                ps += p;
            }
            #pragma unroll
            for (int off = 8; off; off >>= 1)
                ps += __shfl_xor_sync(0xffffffffu, ps, off, 16);
            lrow[r] = lrow[r]*corr + ps;
            mrow[r] = mn;
            #pragma unroll
            for (int c = 0; c < 4; c++) o[r][c] *= corr;
        }

        #pragma unroll
        for (int c = 0; c < 4; c++)
            *(float4*)&Pt[(tx*4 + c)*FA_STR + ty*4] =
                make_float4(s_[0][c], s_[1][c], s_[2][c], s_[3][c]);
        __syncthreads();

        #pragma unroll 8
        for (int k = 0; k < 64; k++) {
            float a[4], vv[4];
            *(float4*)a  = *(const float4*)&Pt[k*FA_STR + ty*4];
            *(float4*)vv = *(const float4*)&Vs[k*FA_STR + tx*4];
            #pragma unroll
            for (int r = 0; r < 4; r++)
                #pragma unroll
                for (int c = 0; c < 4; c++)
                    o[r][c] += a[r]*vv[c];
        }
    }

    #pragma unroll
    for (int r = 0; r < 4; r++) {
        float inv = 1.f / lrow[r];
        size_t orow = ((size_t)(b*MM + m0 + ty*4 + r))*DD + h*DH + tx*4;
        bf162* op = (bf162*)(O + orow);
        op[0] = __floats2bfloat162_rn(o[r][0]*inv, o[r][1]*inv);
        op[1] = __floats2bfloat162_rn(o[r][2]*inv, o[r][3]*inv);
    }
}

// ---------------------------------------------------------------------------
// GEGLU (bf16 in/out, fp32 math)
// ---------------------------------------------------------------------------
__device__ __forceinline__ float gelu_t(float x) {
    float x3 = x*x*x;
    return 0.5f * x * (1.f + tanhf(0.7978845608028654f * (x + 0.044715f*x3)));
}

__global__ __launch_bounds__(256) void geglu_kernel(
    const bf16* __restrict__ h, bf16* __restrict__ g)
{
    size_t i = (size_t)blockIdx.x*256 + threadIdx.x;  // over N * FD/2 = 8388608
    size_t n = i >> 10;        // FD/2 = 1024 pairs per row
    size_t p = i & 1023;
    const bf162* hp = (const bf162*)h;
    bf162 a  = hp[n*2048 + p];
    bf162 c2 = hp[n*2048 + 1024 + p];
    float2 af = __bfloat1622float2(a);
    float2 cf = __bfloat1622float2(c2);
    ((bf162*)g)[n*1024 + p] =
        __floats2bfloat162_rn(gelu_t(af.x)*cf.x, gelu_t(af.y)*cf.y);
}

// ---------------------------------------------------------------------------
// Host launcher
// ---------------------------------------------------------------------------
extern "C" void kernel_launch(void* const* d_in, const int* in_sizes, int n_in,
                              void* d_out, int out_size)
{
    const float* x    = (const float*)d_in[0];
    const int*   mask = (const int*)  d_in[1];
    const float* ln1w = (const float*)d_in[2];
    const float* ln1b = (const float*)d_in[3];
    const float* ln2w = (const float*)d_in[4];
    const float* ln2b = (const float*)d_in[5];
    const float* Uq   = (const float*)d_in[6];
    const float* Uk   = (const float*)d_in[7];
    const float* Uv   = (const float*)d_in[8];
    const float* Vq   = (const float*)d_in[9];
    const float* Vk   = (const float*)d_in[10];
    const float* Vv   = (const float*)d_in[11];
    const float* bq   = (const float*)d_in[12];
    const float* bk   = (const float*)d_in[13];
    const float* bv   = (const float*)d_in[14];
    const float* Wo   = (const float*)d_in[15];
    const float* Wob  = (const float*)d_in[16];
    const float* U1   = (const float*)d_in[17];
    const float* V1   = (const float*)d_in[18];
    const float* b1   = (const float*)d_in[19];
    const float* U2   = (const float*)d_in[20];
    const float* V2   = (const float*)d_in[21];
    const float* b2   = (const float*)d_in[22];
    float* out = (float*)d_out;

    void* p;
    #define SYMF(var, sym) cudaGetSymbolAddress(&p, sym); float* var = (float*)p;
    #define SYMB(var, sym) cudaGetSymbolAddress(&p, sym); bf16* var = (bf16*)p;
    SYMB(bXN,  g_bXN);  SYMB(bPq, g_bPq);  SYMB(bPk, g_bPk);  SYMB(bPv, g_bPv);
    SYMB(bAO,  g_bAO);  SYMB(bXN2,g_bXN2); SYMB(bP2, g_bP2);  SYMB(bHb, g_bHb);
    SYMB(bG,   g_bG);   SYMB(bT,  g_bT);
    SYMB(wUq,  g_wUq);  SYMB(wUk, g_wUk);  SYMB(wUv, g_wUv);
    SYMB(wVq,  g_wVq);  SYMB(wVk, g_wVk);  SYMB(wVv, g_wVv);
    SYMB(wWoT, g_wWoT); SYMB(wU1, g_wU1);  SYMB(wV1, g_wV1);
    SYMB(wU2,  g_wU2);  SYMB(wV2, g_wV2);
    SYMF(Qb,   g_Qb);   SYMF(Kb,  g_Kb);   SYMF(Vb,  g_Vb);
    #undef SYMF
    #undef SYMB

    cudaFuncSetAttribute(fa_kernel,
        cudaFuncAttributeMaxDynamicSharedMemorySize, FA_SMEM);
    cudaFuncSetAttribute(hgemm<false,false,false>,
        cudaFuncAttributeMaxDynamicSharedMemorySize, 65536);
    cudaFuncSetAttribute(hgemm<true,false,true>,
        cudaFuncAttributeMaxDynamicSharedMemorySize, 65536);
    cudaFuncSetAttribute(hgemm<true,true,true>,
        cudaFuncAttributeMaxDynamicSharedMemorySize, 65536);
    cudaFuncSetAttribute(hgemm<true,false,false>,
        cudaFuncAttributeMaxDynamicSharedMemorySize, 65536);

    // Weight conversions (fp32 -> bf16), Wo also transposed
    #define CVT(src, dst, n) f2b_kernel<<<(n)/1024, 256>>>(src, dst)
    CVT(Uq, wUq, DD*RR);  CVT(Uk, wUk, DD*RR);  CVT(Uv, wUv, DD*RR);
    CVT(Vq, wVq, RR*DD);  CVT(Vk, wVk, RR*DD);  CVT(Vv, wVv, RR*DD);
    CVT(U1, wU1, DD*RR1); CVT(V1, wV1, RR1*2*FD);
    CVT(U2, wU2, FD*RR2); CVT(V2, wV2, RR2*DD);
    #undef CVT
    transb_kernel<<<dim3(32,32), 256>>>(Wo, wWoT);

    rope_table_kernel<<<256, 256>>>();

    // LN1 -> bf16
    ln_kernel<<<NN, 256>>>(x, ln1w, ln1b, bXN);

    // Rank projections: [N,1024]@[1024,256] -> bf16
    hgemm<false,false,false><<<dim3(RR/128, NN/128), 256, 65536>>>(bXN, wUq, nullptr, nullptr, bPq, RR, DD);
    hgemm<false,false,false><<<dim3(RR/128, NN/128), 256, 65536>>>(bXN, wUk, nullptr, nullptr, bPk, RR, DD);
    hgemm<false,false,false><<<dim3(RR/128, NN/128), 256, 65536>>>(bXN, wUv, nullptr, nullptr, bPv, RR, DD);

    // Expand + bias: [N,256]@[256,1024] -> fp32 (for RoPE/attention)
    hgemm<true,false,true><<<dim3(DD/128, NN/128), 256, 65536>>>(bPq, wVq, bq, nullptr, Qb, DD, RR);
    hgemm<true,false,true><<<dim3(DD/128, NN/128), 256, 65536>>>(bPk, wVk, bk, nullptr, Kb, DD, RR);
    hgemm<true,false,true><<<dim3(DD/128, NN/128), 256, 65536>>>(bPv, wVv, bv, nullptr, Vb, DD, RR);

    // RoPE on Q, K (fp32, in place)
    rope_kernel<<<(NN*HH*32)/256, 256>>>(Qb, Kb);

    // Attention (fp32 compute) -> bf16 AO
    fa_kernel<<<dim3(MM/64, BB*HH), 256, FA_SMEM>>>(Qb, Kb, Vb, mask, bAO);

    // Out-proj + bias + residual(x) -> d_out fp32
    hgemm<true,true,true><<<dim3(DD/128, NN/128), 256, 65536>>>(bAO, wWoT, Wob, x, out, DD, DD);

    // LN2 -> bf16
    ln_kernel<<<NN, 256>>>(out, ln2w, ln2b, bXN2);

    // FFN rank path
    hgemm<false,false,false><<<dim3(RR1/128, NN/128), 256, 65536>>>(bXN2, wU1, nullptr, nullptr, bP2, RR1, DD);
    hgemm<true,false,false><<<dim3((2*FD)/128, NN/128), 256, 65536>>>(bP2, wV1, b1, nullptr, bHb, 2*FD, RR1);
    geglu_kernel<<<(NN*(FD/2))/256, 256>>>(bHb, bG);
    hgemm<false,false,false><<<dim3(RR2/128, NN/128), 256, 65536>>>(bG, wU2, nullptr, nullptr, bT, RR2, FD);

    // Final: out = out(residual) + T @ V2 + b2 (in-place residual safe:
    // each element read then written by the same thread)
    hgemm<true,true,true><<<dim3(DD/128, NN/128), 256, 65536>>>(bT, wV2, b2, out, out, DD, RR2);
}

// round 7
// speedup vs baseline: 7.1593x; 3.5337x over previous
#include <cuda_runtime.h>
#include <cuda_bf16.h>
#include <math.h>
#include <stdint.h>

// Problem constants
#define BB 4
#define MM 2048
#define DD 1024
#define HH 16
#define DH 64
#define RR 256
#define FD 2048
#define RR1 512
#define RR2 512
#define NN (BB*MM)   // 8192 tokens

typedef __nv_bfloat16 bf16;
typedef __nv_bfloat162 bf162;

// ---------------------------------------------------------------------------
// Scratch (device globals; allocation-free)
// ---------------------------------------------------------------------------
// bf16 activations
__device__ bf16 g_bXN  [NN*DD];
__device__ bf16 g_bPqkv[NN*3*RR];     // packed [N, 768]: Pq|Pk|Pv
__device__ bf16 g_bQ   [NN*DD];
__device__ bf16 g_bK   [NN*DD];
__device__ bf16 g_bV   [NN*DD];
__device__ bf16 g_bAO  [NN*DD];
__device__ bf16 g_bXN2 [NN*DD];
__device__ bf16 g_bP2  [NN*RR1];
__device__ bf16 g_bHb  [NN*2*FD];
__device__ bf16 g_bG   [NN*FD];
__device__ bf16 g_bT   [NN*RR2];
// bf16 weights
__device__ bf16 g_wUqkv[DD*3*RR];     // packed [1024, 768]: Uq|Uk|Uv
__device__ bf16 g_wVq [RR*DD];
__device__ bf16 g_wVk [RR*DD];
__device__ bf16 g_wVv [RR*DD];
__device__ bf16 g_wWoT[DD*DD];
__device__ bf16 g_wU1 [DD*RR1];
__device__ bf16 g_wV1 [RR1*2*FD];
__device__ bf16 g_wU2 [FD*RR2];
__device__ bf16 g_wV2 [RR2*DD];
// fp32 rope tables
__device__ float g_ropeC[MM*32];
__device__ float g_ropeS[MM*32];

// ---------------------------------------------------------------------------
// Small PTX helpers
// ---------------------------------------------------------------------------
__device__ __forceinline__ void cp16(uint32_t dst, const void* src) {
    asm volatile("cp.async.cg.shared.global [%0], [%1], 16;\n" :: "r"(dst), "l"(src));
}
__device__ __forceinline__ void cp_commit() {
    asm volatile("cp.async.commit_group;\n" ::: "memory");
}
__device__ __forceinline__ void ldsm4(uint32_t* r, uint32_t addr) {
    asm volatile("ldmatrix.sync.aligned.m8n8.x4.shared.b16 {%0,%1,%2,%3}, [%4];\n"
        : "=r"(r[0]), "=r"(r[1]), "=r"(r[2]), "=r"(r[3]) : "r"(addr));
}
__device__ __forceinline__ void ldsm4t(uint32_t* r, uint32_t addr) {
    asm volatile("ldmatrix.sync.aligned.m8n8.x4.trans.shared.b16 {%0,%1,%2,%3}, [%4];\n"
        : "=r"(r[0]), "=r"(r[1]), "=r"(r[2]), "=r"(r[3]) : "r"(addr));
}
__device__ __forceinline__ void mma_bf16(float* c, const uint32_t* a, uint32_t b0, uint32_t b1) {
    asm volatile(
        "mma.sync.aligned.m16n8k16.row.col.f32.bf16.bf16.f32 "
        "{%0,%1,%2,%3}, {%4,%5,%6,%7}, {%8,%9}, {%0,%1,%2,%3};\n"
        : "+f"(c[0]), "+f"(c[1]), "+f"(c[2]), "+f"(c[3])
        : "r"(a[0]), "r"(a[1]), "r"(a[2]), "r"(a[3]), "r"(b0), "r"(b1));
}
__device__ __forceinline__ uint32_t packbf(float a, float b) {
    bf162 t = __floats2bfloat162_rn(a, b);
    return *reinterpret_cast<uint32_t*>(&t);
}

// ---------------------------------------------------------------------------
// bf16 tensor-core GEMM: C[M,Nc] = A[M,Kd] @ B[Kd,Nc] (+bias)(+fp32 res)
// A has row stride lda (>= Kd). 128x128x64 tile, 256 threads, cp.async
// double buffer, XOR swizzle, ldmatrix, m16n8k16.
// ---------------------------------------------------------------------------
template<bool BIAS, bool RES, bool F32OUT>
__global__ __launch_bounds__(256, 2) void hgemm(
    const bf16* __restrict__ A, const bf16* __restrict__ B,
    const float* __restrict__ bias, const float* __restrict__ res,
    void* __restrict__ Cout, int Nc, int Kd, int lda)
{
    extern __shared__ char smraw[];
    bf16* As = (bf16*)smraw;               // [2][128*64]
    const int tid = threadIdx.x, lane = tid & 31, wid = tid >> 5;
    const int wm = (wid & 3) << 5;
    const int wn = (wid >> 2) << 6;
    const int m0 = blockIdx.y << 7, n0 = blockIdx.x << 7;
    const int KT = Kd >> 6;

    const uint32_t sA = (uint32_t)__cvta_generic_to_shared(As);
    const uint32_t sB = sA + 32768;        // B tiles after 2 A buffers

    float acc[2][8][4];
    #pragma unroll
    for (int i = 0; i < 2; i++)
        #pragma unroll
        for (int j = 0; j < 8; j++)
            #pragma unroll
            for (int k = 0; k < 4; k++) acc[i][j][k] = 0.f;

    auto issue = [&](int kt, int buf) {
        const int k0 = kt << 6;
        const uint32_t da = sA + buf * 16384;
        #pragma unroll
        for (int t = 0; t < 4; t++) {
            int j = tid + (t << 8);
            int r = j >> 3, c = j & 7;
            const bf16* src = A + (size_t)(m0 + r) * lda + k0 + (c << 3);
            uint32_t dst = da + (((r << 6) + ((c ^ (r & 7)) << 3)) << 1);
            cp16(dst, src);
        }
        const uint32_t db = sB + buf * 16384;
        #pragma unroll
        for (int t = 0; t < 4; t++) {
            int j = tid + (t << 8);
            int r = j >> 4, c = j & 15;
            int swc = (c & 8) | ((c & 7) ^ (r & 7));
            const bf16* src = B + (size_t)(k0 + r) * Nc + n0 + (c << 3);
            uint32_t dst = db + (((r << 7) + (swc << 3)) << 1);
            cp16(dst, src);
        }
    };

    issue(0, 0);
    cp_commit();

    int buf = 0;
    for (int kt = 0; kt < KT; kt++) {
        if (kt + 1 < KT) {
            issue(kt + 1, buf ^ 1);
            cp_commit();
            asm volatile("cp.async.wait_group 1;\n" ::: "memory");
        } else {
            asm volatile("cp.async.wait_group 0;\n" ::: "memory");
        }
        __syncthreads();

        const uint32_t aBase = sA + buf * 16384;
        const uint32_t bBase = sB + buf * 16384;
        #pragma unroll
        for (int ks = 0; ks < 4; ks++) {
            uint32_t afr[2][4];
            #pragma unroll
            for (int mt = 0; mt < 2; mt++) {
                int row = wm + mt * 16 + (lane & 15);
                int ch = 2 * ks + (lane >> 4);
                ldsm4(afr[mt], aBase + (((row << 6) + ((ch ^ (row & 7)) << 3)) << 1));
            }
            uint32_t bfr[4][4];
            #pragma unroll
            for (int nt = 0; nt < 4; nt++) {
                int k = ks * 16 + (lane & 15);
                int ch = (wn >> 3) + nt * 2 + (lane >> 4);
                int swc = (ch & 8) | ((ch & 7) ^ (k & 7));
                ldsm4t(bfr[nt], bBase + (((k << 7) + (swc << 3)) << 1));
            }
            #pragma unroll
            for (int mt = 0; mt < 2; mt++)
                #pragma unroll
                for (int nt = 0; nt < 4; nt++) {
                    mma_bf16(acc[mt][nt*2+0], afr[mt], bfr[nt][0], bfr[nt][1]);
                    mma_bf16(acc[mt][nt*2+1], afr[mt], bfr[nt][2], bfr[nt][3]);
                }
        }
        __syncthreads();
        buf ^= 1;
    }

    const int g = lane >> 2, q = (lane & 3) << 1;
    #pragma unroll
    for (int mt = 0; mt < 2; mt++)
        #pragma unroll
        for (int n8 = 0; n8 < 8; n8++) {
            int n = n0 + wn + n8 * 8 + q;
            float b0 = 0.f, b1 = 0.f;
            if (BIAS) { b0 = bias[n]; b1 = bias[n + 1]; }
            #pragma unroll
            for (int hh = 0; hh < 2; hh++) {
                int m = m0 + wm + mt * 16 + g + hh * 8;
                float v0 = acc[mt][n8][hh*2+0] + b0;
                float v1 = acc[mt][n8][hh*2+1] + b1;
                size_t off = (size_t)m * Nc + n;
                if (RES) {
                    const float* rp = res + off;
                    v0 += rp[0]; v1 += rp[1];
                }
                if (F32OUT) {
                    float* C = (float*)Cout;
                    C[off] = v0; C[off + 1] = v1;
                } else {
                    bf162* C = (bf162*)Cout;
                    C[off >> 1] = __floats2bfloat162_rn(v0, v1);
                }
            }
        }
}

// ---------------------------------------------------------------------------
// Weight conversion fp32 -> bf16
// ---------------------------------------------------------------------------
__global__ __launch_bounds__(256) void f2b_kernel(
    const float* __restrict__ s, bf16* __restrict__ d)
{
    int i = blockIdx.x * 256 + threadIdx.x;   // one float4 per thread
    float4 v = ((const float4*)s)[i];
    ((bf162*)d)[i*2+0] = __floats2bfloat162_rn(v.x, v.y);
    ((bf162*)d)[i*2+1] = __floats2bfloat162_rn(v.z, v.w);
}

// Strided convert: src [rows, srcW] fp32 -> dst[:, colOff:colOff+srcW] bf16,
// dst row width dstW.
__global__ __launch_bounds__(256) void f2b_stride_kernel(
    const float* __restrict__ s, bf16* __restrict__ d,
    int srcW, int dstW, int colOff)
{
    int i = blockIdx.x * 256 + threadIdx.x;   // over rows*srcW/4
    int r = i / (srcW >> 2);
    int c = (i % (srcW >> 2)) << 2;
    float4 v = *(const float4*)&s[(size_t)r * srcW + c];
    bf162* dp = (bf162*)&d[(size_t)r * dstW + colOff + c];
    dp[0] = __floats2bfloat162_rn(v.x, v.y);
    dp[1] = __floats2bfloat162_rn(v.z, v.w);
}

// Transpose-convert: src fp32 [1024 out][1024 in] -> dst bf16 [in][out]
__global__ __launch_bounds__(256) void transb_kernel(
    const float* __restrict__ s, bf16* __restrict__ d)
{
    __shared__ float tile[32][33];
    int bx = blockIdx.x * 32;
    int by = blockIdx.y * 32;
    int tx = threadIdx.x & 31, ty = threadIdx.x >> 5;
    #pragma unroll
    for (int i = 0; i < 4; i++) {
        int row = by + ty + i * 8;
        tile[ty + i * 8][tx] = s[(size_t)row * DD + bx + tx];
    }
    __syncthreads();
    #pragma unroll
    for (int i = 0; i < 4; i++) {
        int orow = bx + ty + i * 8;
        d[(size_t)orow * DD + by + tx] = __float2bfloat16(tile[tx][ty + i * 8]);
    }
}

// ---------------------------------------------------------------------------
// LayerNorm: one block per row (D=1024), 256 threads, writes bf16
// ---------------------------------------------------------------------------
__device__ __forceinline__ float block_sum(float v) {
    __shared__ float sh[8];
    int lane = threadIdx.x & 31, w = threadIdx.x >> 5;
    #pragma unroll
    for (int o = 16; o; o >>= 1) v += __shfl_xor_sync(0xffffffffu, v, o);
    __syncthreads();
    if (lane == 0) sh[w] = v;
    __syncthreads();
    float t = 0.f;
    #pragma unroll
    for (int i = 0; i < 8; i++) t += sh[i];
    return t;
}

__global__ __launch_bounds__(256) void ln_kernel(
    const float* __restrict__ x, const float* __restrict__ w,
    const float* __restrict__ b, bf16* __restrict__ out)
{
    size_t row = blockIdx.x;
    int t = threadIdx.x;
    float4 v = ((const float4*)(x + row*DD))[t];
    float mu = block_sum(v.x + v.y + v.z + v.w) * (1.f/1024.f);
    float dx = v.x - mu, dy = v.y - mu, dz = v.z - mu, dw = v.w - mu;
    float var = block_sum(dx*dx + dy*dy + dz*dz + dw*dw) * (1.f/1024.f);
    float rs = rsqrtf(var + 1e-5f);
    float4 wv = ((const float4*)w)[t];
    float4 bv = ((const float4*)b)[t];
    bf162* o2 = (bf162*)(out + row*DD);
    o2[t*2+0] = __floats2bfloat162_rn(dx*rs*wv.x + bv.x, dy*rs*wv.y + bv.y);
    o2[t*2+1] = __floats2bfloat162_rn(dz*rs*wv.z + bv.z, dw*rs*wv.w + bv.w);
}

// ---------------------------------------------------------------------------
// RoPE
// ---------------------------------------------------------------------------
__global__ void rope_table_kernel() {
    int idx = blockIdx.x*256 + threadIdx.x;   // 65536 = 2048*32
    int m = idx >> 5, i = idx & 31;
    double e = (double)(2*i) / 64.0;
    float invf = (float)(1.0 / pow(10000.0, e));
    float ang = (float)m * invf;
    double a = (double)ang;
    g_ropeC[idx] = (float)cos(a);
    g_ropeS[idx] = (float)sin(a);
}

// In-place RoPE on bf16 Q and K; one thread per bf162 pair in the low half.
__global__ __launch_bounds__(256) void rope_bf16_kernel(
    bf16* __restrict__ Q, bf16* __restrict__ K)
{
    int idx = blockIdx.x*256 + threadIdx.x;   // NN*HH*16 = 2097152
    int n = idx >> 8;
    int r = idx & 255;
    int h = r >> 4;
    int i2 = (r & 15) << 1;                   // 0,2,...,30
    int m = n & (MM - 1);
    float c0 = g_ropeC[m*32 + i2],     s0 = g_ropeS[m*32 + i2];
    float c1 = g_ropeC[m*32 + i2 + 1], s1 = g_ropeS[m*32 + i2 + 1];
    size_t base = (size_t)n*DD + h*DH;
    bf162* Qp = (bf162*)(Q + base);
    bf162* Kp = (bf162*)(K + base);
    int p = i2 >> 1;
    float2 qa = __bfloat1622float2(Qp[p]);
    float2 qb = __bfloat1622float2(Qp[p + 16]);
    Qp[p]      = __floats2bfloat162_rn(qa.x*c0 - qb.x*s0, qa.y*c1 - qb.y*s1);
    Qp[p + 16] = __floats2bfloat162_rn(qb.x*c0 + qa.x*s0, qb.y*c1 + qa.y*s1);
    float2 ka = __bfloat1622float2(Kp[p]);
    float2 kb = __bfloat1622float2(Kp[p + 16]);
    Kp[p]      = __floats2bfloat162_rn(ka.x*c0 - kb.x*s0, ka.y*c1 - kb.y*s1);
    Kp[p + 16] = __floats2bfloat162_rn(kb.x*c0 + ka.x*s0, kb.y*c1 + ka.y*s1);
}

// ---------------------------------------------------------------------------
// bf16 tensor-core flash attention.
// CTA: 128 queries x one (b,h). 8 warps, 16 query rows each. KV tile 64.
// Q frags register-resident; S and O via m16n8k16; online softmax in regs;
// P repacked register-to-register (C-layout -> A-layout).
// smem: Qs 16KB | K 2x8KB | V 2x8KB | maskbias 2x64 f32  (49664 B)
// ---------------------------------------------------------------------------
#define FAB_SMEM 49664

__global__ __launch_bounds__(256) void fa_bf16_kernel(
    const bf16* __restrict__ Q, const bf16* __restrict__ K,
    const bf16* __restrict__ V, const int* __restrict__ mask,
    bf16* __restrict__ O)
{
    extern __shared__ char fasm[];
    const uint32_t sQ = (uint32_t)__cvta_generic_to_shared(fasm);
    const uint32_t sK = sQ + 16384;
    const uint32_t sV = sQ + 32768;
    float* maskb = (float*)(fasm + 49152);

    const int tid = threadIdx.x, lane = tid & 31, wid = tid >> 5;
    const int m0 = blockIdx.x * 128;
    const int b = blockIdx.y >> 4, h = blockIdx.y & 15;

    // Q tile load (128x64), swizzled
    {
        const bf16* Qg = Q + ((size_t)(b*MM + m0))*DD + h*DH;
        #pragma unroll
        for (int t = 0; t < 4; t++) {
            int j = tid + (t << 8);
            int r = j >> 3, c = j & 7;
            cp16(sQ + (((r << 6) + ((c ^ (r & 7)) << 3)) << 1),
                 Qg + (size_t)r*DD + (c << 3));
        }
        cp_commit();
    }

    auto issueKV = [&](int tkv, int bb) {
        size_t base = ((size_t)(b*MM + tkv*64))*DD + h*DH;
        #pragma unroll
        for (int t = 0; t < 2; t++) {
            int j = tid + (t << 8);
            int r = j >> 3, c = j & 7;
            uint32_t off = (((r << 6) + ((c ^ (r & 7)) << 3)) << 1) + bb*8192;
            cp16(sK + off, K + base + (size_t)r*DD + (c << 3));
            cp16(sV + off, V + base + (size_t)r*DD + (c << 3));
        }
        if (tid < 64)
            maskb[bb*64 + tid] = mask[b*MM + tkv*64 + tid] ? 0.f : -1e30f;
    };

    issueKV(0, 0);
    cp_commit();
    asm volatile("cp.async.wait_group 0;\n" ::: "memory");
    __syncthreads();

    // Q fragments (4 k-steps of 16 over DH=64)
    uint32_t qf[4][4];
    {
        int row = (wid << 4) + (lane & 15);
        #pragma unroll
        for (int ks = 0; ks < 4; ks++) {
            int ch = 2*ks + (lane >> 4);
            ldsm4(qf[ks], sQ + (((row << 6) + ((ch ^ (row & 7)) << 3)) << 1));
        }
    }

    float o_acc[8][4];
    #pragma unroll
    for (int i = 0; i < 8; i++)
        #pragma unroll
        for (int j = 0; j < 4; j++) o_acc[i][j] = 0.f;
    float mrow[2] = {-1e30f, -1e30f}, lrow[2] = {0.f, 0.f};

    int buf = 0;
    for (int t = 0; t < MM/64; t++) {
        if (t + 1 < MM/64) { issueKV(t + 1, buf ^ 1); cp_commit(); }

        // ---- S = Q K^T (scaled later) ----
        float s_acc[8][4];
        #pragma unroll
        for (int i = 0; i < 8; i++)
            #pragma unroll
            for (int j = 0; j < 4; j++) s_acc[i][j] = 0.f;

        const uint32_t kb = sK + buf*8192;
        #pragma unroll
        for (int ks = 0; ks < 4; ks++) {
            #pragma unroll
            for (int kvt = 0; kvt < 4; kvt++) {
                uint32_t kf[4];
                int row = (kvt << 4) + (lane & 15);
                int ch = 2*ks + (lane >> 4);
                ldsm4(kf, kb + (((row << 6) + ((ch ^ (row & 7)) << 3)) << 1));
                // K [kv][d] row-major == col-major B; n-tiles kv0-7 / kv8-15
                mma_bf16(s_acc[kvt*2+0], qf[ks], kf[0], kf[2]);
                mma_bf16(s_acc[kvt*2+1], qf[ks], kf[1], kf[3]);
            }
        }

        // ---- online softmax (rows lane>>2 and +8) ----
        const float* mbuf = maskb + buf*64;
        float bias0[8], bias1[8];
        #pragma unroll
        for (int tl = 0; tl < 8; tl++) {
            bias0[tl] = mbuf[tl*8 + ((lane & 3) << 1)];
            bias1[tl] = mbuf[tl*8 + ((lane & 3) << 1) + 1];
        }
        #pragma unroll
        for (int hh = 0; hh < 2; hh++) {
            float mx = -1e30f;
            #pragma unroll
            for (int tl = 0; tl < 8; tl++) {
                float v0 = s_acc[tl][hh*2+0]*0.125f + bias0[tl];
                float v1 = s_acc[tl][hh*2+1]*0.125f + bias1[tl];
                s_acc[tl][hh*2+0] = v0; s_acc[tl][hh*2+1] = v1;
                mx = fmaxf(mx, fmaxf(v0, v1));
            }
            mx = fmaxf(mx, __shfl_xor_sync(0xffffffffu, mx, 1));
            mx = fmaxf(mx, __shfl_xor_sync(0xffffffffu, mx, 2));
            float mn = fmaxf(mrow[hh], mx);
            float corr = __expf(mrow[hh] - mn);
            mrow[hh] = mn;
            float ps = 0.f;
            #pragma unroll
            for (int tl = 0; tl < 8; tl++) {
                float p0 = __expf(s_acc[tl][hh*2+0] - mn);
                float p1 = __expf(s_acc[tl][hh*2+1] - mn);
                s_acc[tl][hh*2+0] = p0; s_acc[tl][hh*2+1] = p1;
                ps += p0 + p1;
            }
            ps += __shfl_xor_sync(0xffffffffu, ps, 1);
            ps += __shfl_xor_sync(0xffffffffu, ps, 2);
            lrow[hh] = lrow[hh]*corr + ps;
            #pragma unroll
            for (int tl = 0; tl < 8; tl++) {
                o_acc[tl][hh*2+0] *= corr;
                o_acc[tl][hh*2+1] *= corr;
            }
        }

        // ---- P: C-layout -> A-layout, bf16 ----
        uint32_t ap[4][4];
        #pragma unroll
        for (int j = 0; j < 4; j++) {
            ap[j][0] = packbf(s_acc[2*j][0],   s_acc[2*j][1]);
            ap[j][1] = packbf(s_acc[2*j][2],   s_acc[2*j][3]);
            ap[j][2] = packbf(s_acc[2*j+1][0], s_acc[2*j+1][1]);
            ap[j][3] = packbf(s_acc[2*j+1][2], s_acc[2*j+1][3]);
        }

        // ---- O += P V ----
        const uint32_t vb = sV + buf*8192;
        #pragma unroll
        for (int j = 0; j < 4; j++) {
            #pragma unroll
            for (int nt = 0; nt < 4; nt++) {
                uint32_t vf[4];
                int krow = (j << 4) + (lane & 15);
                int ch = nt*2 + (lane >> 4);
                ldsm4t(vf, vb + (((krow << 6) + ((ch ^ (krow & 7)) << 3)) << 1));
                mma_bf16(o_acc[nt*2+0], ap[j], vf[0], vf[1]);
                mma_bf16(o_acc[nt*2+1], ap[j], vf[2], vf[3]);
            }
        }

        asm volatile("cp.async.wait_group 0;\n" ::: "memory");
        __syncthreads();
        buf ^= 1;
    }

    // ---- epilogue: O / l -> bf16 ----
    #pragma unroll
    for (int hh = 0; hh < 2; hh++) {
        float inv = 1.f / lrow[hh];
        int token = b*MM + m0 + (wid << 4) + (lane >> 2) + hh*8;
        size_t rowoff = (size_t)token*DD + h*DH + ((lane & 3) << 1);
        #pragma unroll
        for (int tl = 0; tl < 8; tl++) {
            *(bf162*)&O[rowoff + tl*8] =
                __floats2bfloat162_rn(o_acc[tl][hh*2+0]*inv, o_acc[tl][hh*2+1]*inv);
        }
    }
}

// ---------------------------------------------------------------------------
// GEGLU (bf16 in/out, fp32 math)
// ---------------------------------------------------------------------------
__device__ __forceinline__ float gelu_t(float x) {
    float x3 = x*x*x;
    return 0.5f * x * (1.f + tanhf(0.7978845608028654f * (x + 0.044715f*x3)));
}

__global__ __launch_bounds__(256) void geglu_kernel(
    const bf16* __restrict__ h, bf16* __restrict__ g)
{
    size_t i = (size_t)blockIdx.x*256 + threadIdx.x;  // over N * FD/2 = 8388608
    size_t n = i >> 10;
    size_t p = i & 1023;
    const bf162* hp = (const bf162*)h;
    bf162 a  = hp[n*2048 + p];
    bf162 c2 = hp[n*2048 + 1024 + p];
    float2 af = __bfloat1622float2(a);
    float2 cf = __bfloat1622float2(c2);
    ((bf162*)g)[n*1024 + p] =
        __floats2bfloat162_rn(gelu_t(af.x)*cf.x, gelu_t(af.y)*cf.y);
}

// ---------------------------------------------------------------------------
// Host launcher
// ---------------------------------------------------------------------------
extern "C" void kernel_launch(void* const* d_in, const int* in_sizes, int n_in,
                              void* d_out, int out_size)
{
    const float* x    = (const float*)d_in[0];
    const int*   mask = (const int*)  d_in[1];
    const float* ln1w = (const float*)d_in[2];
    const float* ln1b = (const float*)d_in[3];
    const float* ln2w = (const float*)d_in[4];
    const float* ln2b = (const float*)d_in[5];
    const float* Uq   = (const float*)d_in[6];
    const float* Uk   = (const float*)d_in[7];
    const float* Uv   = (const float*)d_in[8];
    const float* Vq   = (const float*)d_in[9];
    const float* Vk   = (const float*)d_in[10];
    const float* Vv   = (const float*)d_in[11];
    const float* bq   = (const float*)d_in[12];
    const float* bk   = (const float*)d_in[13];
    const float* bv   = (const float*)d_in[14];
    const float* Wo   = (const float*)d_in[15];
    const float* Wob  = (const float*)d_in[16];
    const float* U1   = (const float*)d_in[17];
    const float* V1   = (const float*)d_in[18];
    const float* b1   = (const float*)d_in[19];
    const float* U2   = (const float*)d_in[20];
    const float* V2   = (const float*)d_in[21];
    const float* b2   = (const float*)d_in[22];
    float* out = (float*)d_out;

    void* p;
    #define SYMB(var, sym) cudaGetSymbolAddress(&p, sym); bf16* var = (bf16*)p;
    SYMB(bXN,  g_bXN);   SYMB(bPqkv, g_bPqkv);
    SYMB(bQ,   g_bQ);    SYMB(bK,  g_bK);   SYMB(bV,  g_bV);
    SYMB(bAO,  g_bAO);   SYMB(bXN2,g_bXN2); SYMB(bP2, g_bP2);
    SYMB(bHb,  g_bHb);   SYMB(bG,  g_bG);   SYMB(bT,  g_bT);
    SYMB(wUqkv,g_wUqkv);
    SYMB(wVq,  g_wVq);   SYMB(wVk, g_wVk);  SYMB(wVv, g_wVv);
    SYMB(wWoT, g_wWoT);  SYMB(wU1, g_wU1);  SYMB(wV1, g_wV1);
    SYMB(wU2,  g_wU2);   SYMB(wV2, g_wV2);
    #undef SYMB

    cudaFuncSetAttribute(fa_bf16_kernel,
        cudaFuncAttributeMaxDynamicSharedMemorySize, FAB_SMEM);
    cudaFuncSetAttribute(hgemm<false,false,false>,
        cudaFuncAttributeMaxDynamicSharedMemorySize, 65536);
    cudaFuncSetAttribute(hgemm<true,false,false>,
        cudaFuncAttributeMaxDynamicSharedMemorySize, 65536);
    cudaFuncSetAttribute(hgemm<true,true,true>,
        cudaFuncAttributeMaxDynamicSharedMemorySize, 65536);

    // Weight conversions
    #define CVT(src, dst, n) f2b_kernel<<<(n)/1024, 256>>>(src, dst)
    CVT(Vq, wVq, RR*DD);  CVT(Vk, wVk, RR*DD);  CVT(Vv, wVv, RR*DD);
    CVT(U1, wU1, DD*RR1); CVT(V1, wV1, RR1*2*FD);
    CVT(U2, wU2, FD*RR2); CVT(V2, wV2, RR2*DD);
    #undef CVT
    f2b_stride_kernel<<<(DD*RR/4)/256, 256>>>(Uq, wUqkv, RR, 3*RR, 0);
    f2b_stride_kernel<<<(DD*RR/4)/256, 256>>>(Uk, wUqkv, RR, 3*RR, RR);
    f2b_stride_kernel<<<(DD*RR/4)/256, 256>>>(Uv, wUqkv, RR, 3*RR, 2*RR);
    transb_kernel<<<dim3(32,32), 256>>>(Wo, wWoT);

    rope_table_kernel<<<256, 256>>>();

    // LN1 -> bf16
    ln_kernel<<<NN, 256>>>(x, ln1w, ln1b, bXN);

    // Merged rank projection: [N,1024]@[1024,768] -> bPqkv
    hgemm<false,false,false><<<dim3(3*RR/128, NN/128), 256, 65536>>>(
        bXN, wUqkv, nullptr, nullptr, bPqkv, 3*RR, DD, DD);

    // Expand + bias: [N,256]@[256,1024] -> bf16 Q/K/V (A strided in bPqkv)
    hgemm<true,false,false><<<dim3(DD/128, NN/128), 256, 65536>>>(
        bPqkv + 0,    wVq, bq, nullptr, bQ, DD, RR, 3*RR);
    hgemm<true,false,false><<<dim3(DD/128, NN/128), 256, 65536>>>(
        bPqkv + RR,   wVk, bk, nullptr, bK, DD, RR, 3*RR);
    hgemm<true,false,false><<<dim3(DD/128, NN/128), 256, 65536>>>(
        bPqkv + 2*RR, wVv, bv, nullptr, bV, DD, RR, 3*RR);

    // RoPE in place on bf16 Q, K
    rope_bf16_kernel<<<(NN*HH*16)/256, 256>>>(bQ, bK);

    // bf16 flash attention -> bAO
    fa_bf16_kernel<<<dim3(MM/128, BB*HH), 256, FAB_SMEM>>>(bQ, bK, bV, mask, bAO);

    // Out-proj + bias + residual(x) -> d_out fp32
    hgemm<true,true,true><<<dim3(DD/128, NN/128), 256, 65536>>>(
        bAO, wWoT, Wob, x, out, DD, DD, DD);

    // LN2 -> bf16
    ln_kernel<<<NN, 256>>>(out, ln2w, ln2b, bXN2);

    // FFN rank path
    hgemm<false,false,false><<<dim3(RR1/128, NN/128), 256, 65536>>>(
        bXN2, wU1, nullptr, nullptr, bP2, RR1, DD, DD);
    hgemm<true,false,false><<<dim3((2*FD)/128, NN/128), 256, 65536>>>(
        bP2, wV1, b1, nullptr, bHb, 2*FD, RR1, RR1);
    geglu_kernel<<<(NN*(FD/2))/256, 256>>>(bHb, bG);
    hgemm<false,false,false><<<dim3(RR2/128, NN/128), 256, 65536>>>(
        bG, wU2, nullptr, nullptr, bT, RR2, FD, FD);

    // Final: out = out(residual) + T @ V2 + b2 (in-place residual safe:
    // each element read then written by the same thread)
    hgemm<true,true,true><<<dim3(DD/128, NN/128), 256, 65536>>>(
        bT, wV2, b2, out, out, DD, RR2, RR2);
}

// round 9
// speedup vs baseline: 7.4130x; 1.0354x over previous
#include <cuda_runtime.h>
#include <cuda_bf16.h>
#include <math.h>
#include <stdint.h>

// Problem constants
#define BB 4
#define MM 2048
#define DD 1024
#define HH 16
#define DH 64
#define RR 256
#define FD 2048
#define RR1 512
#define RR2 512
#define NN (BB*MM)   // 8192 tokens

typedef __nv_bfloat16 bf16;
typedef __nv_bfloat162 bf162;

// ---------------------------------------------------------------------------
// Scratch (device globals; allocation-free)
// ---------------------------------------------------------------------------
// bf16 activations
__device__ bf16 g_bXN  [NN*DD];
__device__ bf16 g_bPqkv[NN*3*RR];     // packed [N, 768]: Pq|Pk|Pv
__device__ bf16 g_bQ   [NN*DD];
__device__ bf16 g_bK   [NN*DD];
__device__ bf16 g_bV   [NN*DD];
__device__ bf16 g_bAO  [NN*DD];
__device__ bf16 g_bXN2 [NN*DD];
__device__ bf16 g_bP2  [NN*RR1];
__device__ bf16 g_bG   [NN*FD];
__device__ bf16 g_bT   [NN*RR2];
// bf16 weights ([K, N] row-major, as consumed by hgemm's B path)
__device__ bf16 g_wUqkv[DD*3*RR];     // packed [1024, 768]: Uq|Uk|Uv
__device__ bf16 g_wVq [RR*DD];
__device__ bf16 g_wVk [RR*DD];
__device__ bf16 g_wVv [RR*DD];
__device__ bf16 g_wWoT[DD*DD];
__device__ bf16 g_wU1 [DD*RR1];
__device__ bf16 g_wV1P[RR1*2*FD];     // V1 with columns permuted for GEGLU fusion
__device__ bf16 g_wU2 [FD*RR2];
__device__ bf16 g_wV2 [RR2*DD];
// fp32 rope tables
__device__ float g_ropeC[MM*32];
__device__ float g_ropeS[MM*32];

// ---------------------------------------------------------------------------
// Small PTX helpers
// ---------------------------------------------------------------------------
__device__ __forceinline__ void cp16(uint32_t dst, const void* src) {
    asm volatile("cp.async.cg.shared.global [%0], [%1], 16;\n" :: "r"(dst), "l"(src));
}
__device__ __forceinline__ void cp_commit() {
    asm volatile("cp.async.commit_group;\n" ::: "memory");
}
__device__ __forceinline__ void ldsm4(uint32_t* r, uint32_t addr) {
    asm volatile("ldmatrix.sync.aligned.m8n8.x4.shared.b16 {%0,%1,%2,%3}, [%4];\n"
        : "=r"(r[0]), "=r"(r[1]), "=r"(r[2]), "=r"(r[3]) : "r"(addr));
}
__device__ __forceinline__ void ldsm4t(uint32_t* r, uint32_t addr) {
    asm volatile("ldmatrix.sync.aligned.m8n8.x4.trans.shared.b16 {%0,%1,%2,%3}, [%4];\n"
        : "=r"(r[0]), "=r"(r[1]), "=r"(r[2]), "=r"(r[3]) : "r"(addr));
}
__device__ __forceinline__ void mma_bf16(float* c, const uint32_t* a, uint32_t b0, uint32_t b1) {
    asm volatile(
        "mma.sync.aligned.m16n8k16.row.col.f32.bf16.bf16.f32 "
        "{%0,%1,%2,%3}, {%4,%5,%6,%7}, {%8,%9}, {%0,%1,%2,%3};\n"
        : "+f"(c[0]), "+f"(c[1]), "+f"(c[2]), "+f"(c[3])
        : "r"(a[0]), "r"(a[1]), "r"(a[2]), "r"(a[3]), "r"(b0), "r"(b1));
}
__device__ __forceinline__ uint32_t packbf(float a, float b) {
    bf162 t = __floats2bfloat162_rn(a, b);
    return *reinterpret_cast<uint32_t*>(&t);
}

__device__ __forceinline__ float gelu_t(float x) {
    float x3 = x*x*x;
    return 0.5f * x * (1.f + tanhf(0.7978845608028654f * (x + 0.044715f*x3)));
}

// ---------------------------------------------------------------------------
// bf16 tensor-core GEMM: C[M,Nc] = A[M,Kd] @ B[Kd,Nc] (+bias)(+fp32 res)
// A row stride lda (>= Kd). 128x128x64 tile, 256 threads (8 warps, warp tile
// 32x64), cp.async double buffer, XOR swizzle, ldmatrix, m16n8k16.
// ---------------------------------------------------------------------------
#define HG_MAIN_LOOP                                                          \
    issue(0, 0);                                                              \
    cp_commit();                                                              \
    int buf = 0;                                                              \
    for (int kt = 0; kt < KT; kt++) {                                         \
        if (kt + 1 < KT) {                                                    \
            issue(kt + 1, buf ^ 1);                                           \
            cp_commit();                                                      \
            asm volatile("cp.async.wait_group 1;\n" ::: "memory");            \
        } else {                                                              \
            asm volatile("cp.async.wait_group 0;\n" ::: "memory");            \
        }                                                                     \
        __syncthreads();                                                      \
        const uint32_t aBase = sA + buf * 16384;                              \
        const uint32_t bBase = sB + buf * 16384;                              \
        _Pragma("unroll")                                                     \
        for (int ks = 0; ks < 4; ks++) {                                      \
            uint32_t afr[2][4];                                               \
            _Pragma("unroll")                                                 \
            for (int mt = 0; mt < 2; mt++) {                                  \
                int row = wm + mt * 16 + (lane & 15);                         \
                int ch = 2 * ks + (lane >> 4);                                \
                ldsm4(afr[mt], aBase + (((row << 6) + ((ch ^ (row & 7)) << 3)) << 1)); \
            }                                                                 \
            uint32_t bfr[4][4];                                               \
            _Pragma("unroll")                                                 \
            for (int nt = 0; nt < 4; nt++) {                                  \
                int k = ks * 16 + (lane & 15);                                \
                int ch = (wn >> 3) + nt * 2 + (lane >> 4);                    \
                int swc = (ch & 8) | ((ch & 7) ^ (k & 7));                    \
                ldsm4t(bfr[nt], bBase + (((k << 7) + (swc << 3)) << 1));      \
            }                                                                 \
            _Pragma("unroll")                                                 \
            for (int mt = 0; mt < 2; mt++)                                    \
                _Pragma("unroll")                                             \
                for (int nt = 0; nt < 4; nt++) {                              \
                    mma_bf16(acc[mt][nt*2+0], afr[mt], bfr[nt][0], bfr[nt][1]); \
                    mma_bf16(acc[mt][nt*2+1], afr[mt], bfr[nt][2], bfr[nt][3]); \
                }                                                             \
        }                                                                     \
        __syncthreads();                                                      \
        buf ^= 1;                                                             \
    }

template<bool BIAS, bool RES, bool F32OUT>
__global__ __launch_bounds__(256, 2) void hgemm(
    const bf16* __restrict__ A, const bf16* __restrict__ B,
    const float* __restrict__ bias, const float* __restrict__ res,
    void* __restrict__ Cout, int Nc, int Kd, int lda)
{
    extern __shared__ char smraw[];
    const int tid = threadIdx.x, lane = tid & 31, wid = tid >> 5;
    const int wm = (wid & 3) << 5;
    const int wn = (wid >> 2) << 6;
    const int m0 = blockIdx.y << 7, n0 = blockIdx.x << 7;
    const int KT = Kd >> 6;
    const uint32_t sA = (uint32_t)__cvta_generic_to_shared(smraw);
    const uint32_t sB = sA + 32768;

    float acc[2][8][4];
    #pragma unroll
    for (int i = 0; i < 2; i++)
        #pragma unroll
        for (int j = 0; j < 8; j++)
            #pragma unroll
            for (int k = 0; k < 4; k++) acc[i][j][k] = 0.f;

    auto issue = [&](int kt, int b) {
        const int k0 = kt << 6;
        const uint32_t da = sA + b * 16384;
        #pragma unroll
        for (int t = 0; t < 4; t++) {
            int j = tid + (t << 8);
            int r = j >> 3, c = j & 7;
            cp16(da + (((r << 6) + ((c ^ (r & 7)) << 3)) << 1),
                 A + (size_t)(m0 + r) * lda + k0 + (c << 3));
        }
        const uint32_t db = sB + b * 16384;
        #pragma unroll
        for (int t = 0; t < 4; t++) {
            int j = tid + (t << 8);
            int r = j >> 4, c = j & 15;
            int swc = (c & 8) | ((c & 7) ^ (r & 7));
            cp16(db + (((r << 7) + (swc << 3)) << 1),
                 B + (size_t)(k0 + r) * Nc + n0 + (c << 3));
        }
    };

    HG_MAIN_LOOP

    const int g = lane >> 2, q = (lane & 3) << 1;
    #pragma unroll
    for (int mt = 0; mt < 2; mt++)
        #pragma unroll
        for (int n8 = 0; n8 < 8; n8++) {
            int n = n0 + wn + n8 * 8 + q;
            float b0 = 0.f, b1 = 0.f;
            if (BIAS) { b0 = bias[n]; b1 = bias[n + 1]; }
            #pragma unroll
            for (int hh = 0; hh < 2; hh++) {
                int m = m0 + wm + mt * 16 + g + hh * 8;
                float v0 = acc[mt][n8][hh*2+0] + b0;
                float v1 = acc[mt][n8][hh*2+1] + b1;
                size_t off = (size_t)m * Nc + n;
                if (RES) {
                    const float* rp = res + off;
                    v0 += rp[0]; v1 += rp[1];
                }
                if (F32OUT) {
                    float* C = (float*)Cout;
                    C[off] = v0; C[off + 1] = v1;
                } else {
                    bf162* C = (bf162*)Cout;
                    C[off >> 1] = __floats2bfloat162_rn(v0, v1);
                }
            }
        }
}

// ---------------------------------------------------------------------------
// GEGLU-fused GEMM for the V1 expand:
//   H[M, 4096] = A @ B'  where B' = V1 with columns permuted at 32-granularity
//   (new 64-block = [32 h1-cols | 32 h2-cols] of the same gate indices), then
//   G[M, 2048] : g = gelu_tanh(h1 + b1a) * (h2 + b1b), all in registers.
// Each warp's acc holds h1 at n8 (0..3) and the matching h2 at n8+4 in the
// SAME thread/lane -> no smem exchange.
// ---------------------------------------------------------------------------
__global__ __launch_bounds__(256, 2) void hgemm_geglu(
    const bf16* __restrict__ A, const bf16* __restrict__ B,
    const float* __restrict__ bias,         // b1, original index space [2*FD]
    bf16* __restrict__ G, int Nc, int Kd, int lda)
{
    extern __shared__ char smraw[];
    const int tid = threadIdx.x, lane = tid & 31, wid = tid >> 5;
    const int wm = (wid & 3) << 5;
    const int wn = (wid >> 2) << 6;
    const int m0 = blockIdx.y << 7, n0 = blockIdx.x << 7;
    const int KT = Kd >> 6;
    const uint32_t sA = (uint32_t)__cvta_generic_to_shared(smraw);
    const uint32_t sB = sA + 32768;

    float acc[2][8][4];
    #pragma unroll
    for (int i = 0; i < 2; i++)
        #pragma unroll
        for (int j = 0; j < 8; j++)
            #pragma unroll
            for (int k = 0; k < 4; k++) acc[i][j][k] = 0.f;

    auto issue = [&](int kt, int b) {
        const int k0 = kt << 6;
        const uint32_t da = sA + b * 16384;
        #pragma unroll
        for (int t = 0; t < 4; t++) {
            int j = tid + (t << 8);
            int r = j >> 3, c = j & 7;
            cp16(da + (((r << 6) + ((c ^ (r & 7)) << 3)) << 1),
                 A + (size_t)(m0 + r) * lda + k0 + (c << 3));
        }
        const uint32_t db = sB + b * 16384;
        #pragma unroll
        for (int t = 0; t < 4; t++) {
            int j = tid + (t << 8);
            int r = j >> 4, c = j & 15;
            int swc = (c & 8) | ((c & 7) ^ (r & 7));
            cp16(db + (((r << 7) + (swc << 3)) << 1),
                 B + (size_t)(k0 + r) * Nc + n0 + (c << 3));
        }
    };

    HG_MAIN_LOOP

    // GEGLU epilogue: 64-block index for this warp's columns
    const int g = lane >> 2, q = (lane & 3) << 1;
    const int t32 = (n0 + wn) >> 6;             // which 64-block
    const float* b1a = bias + t32 * 32;         // h1 biases
    const float* b1b = bias + FD + t32 * 32;    // h2 biases
    #pragma unroll
    for (int n8 = 0; n8 < 4; n8++) {
        int j = n8 * 8 + q;                     // local gate index 0..31
        float ba0 = b1a[j],     ba1 = b1a[j + 1];
        float bb0 = b1b[j],     bb1 = b1b[j + 1];
        int gc = t32 * 32 + j;                  // global gate column
        #pragma unroll
        for (int mt = 0; mt < 2; mt++)
            #pragma unroll
            for (int hh = 0; hh < 2; hh++) {
                int m = m0 + wm + mt * 16 + g + hh * 8;
                float h10 = acc[mt][n8][hh*2+0] + ba0;
                float h11 = acc[mt][n8][hh*2+1] + ba1;
                float h20 = acc[mt][n8+4][hh*2+0] + bb0;
                float h21 = acc[mt][n8+4][hh*2+1] + bb1;
                *(bf162*)&G[(size_t)m * FD + gc] =
                    __floats2bfloat162_rn(gelu_t(h10)*h20, gelu_t(h11)*h21);
            }
    }
}

// ---------------------------------------------------------------------------
// Weight conversions
// ---------------------------------------------------------------------------
__global__ __launch_bounds__(256) void f2b_kernel(
    const float* __restrict__ s, bf16* __restrict__ d)
{
    int i = blockIdx.x * 256 + threadIdx.x;   // one float4 per thread
    float4 v = ((const float4*)s)[i];
    ((bf162*)d)[i*2+0] = __floats2bfloat162_rn(v.x, v.y);
    ((bf162*)d)[i*2+1] = __floats2bfloat162_rn(v.z, v.w);
}

// Strided convert: src [rows, srcW] fp32 -> dst[:, colOff:colOff+srcW] bf16.
__global__ __launch_bounds__(256) void f2b_stride_kernel(
    const float* __restrict__ s, bf16* __restrict__ d,
    int srcW, int dstW, int colOff)
{
    int i = blockIdx.x * 256 + threadIdx.x;
    int r = i / (srcW >> 2);
    int c = (i % (srcW >> 2)) << 2;
    float4 v = *(const float4*)&s[(size_t)r * srcW + c];
    bf162* dp = (bf162*)&d[(size_t)r * dstW + colOff + c];
    dp[0] = __floats2bfloat162_rn(v.x, v.y);
    dp[1] = __floats2bfloat162_rn(v.z, v.w);
}

// V1 GEGLU permute-convert: dst col c <- src col orig(c), 32-col blocks:
// t32=c>>6, w=c&63; orig = w<32 ? t32*32+w : FD + t32*32 + (w-32).
__global__ __launch_bounds__(256) void f2b_geglu_kernel(
    const float* __restrict__ s, bf16* __restrict__ d)
{
    int i = blockIdx.x * 256 + threadIdx.x;   // over RR1 * 2FD / 4
    int r = i >> 10;                           // 4096/4 = 1024 float4 per row
    int c = (i & 1023) << 2;
    int t32 = c >> 6, w = c & 63;
    int orig = (w < 32) ? (t32*32 + w) : (FD + t32*32 + (w - 32));
    float4 v = *(const float4*)&s[(size_t)r * (2*FD) + orig];
    bf162* dp = (bf162*)&d[(size_t)r * (2*FD) + c];
    dp[0] = __floats2bfloat162_rn(v.x, v.y);
    dp[1] = __floats2bfloat162_rn(v.z, v.w);
}

// Transpose-convert: src fp32 [1024 out][1024 in] -> dst bf16 [in][out]
__global__ __launch_bounds__(256) void transb_kernel(
    const float* __restrict__ s, bf16* __restrict__ d)
{
    __shared__ float tile[32][33];
    int bx = blockIdx.x * 32;
    int by = blockIdx.y * 32;
    int tx = threadIdx.x & 31, ty = threadIdx.x >> 5;
    #pragma unroll
    for (int i = 0; i < 4; i++) {
        int row = by + ty + i * 8;
        tile[ty + i * 8][tx] = s[(size_t)row * DD + bx + tx];
    }
    __syncthreads();
    #pragma unroll
    for (int i = 0; i < 4; i++) {
        int orow = bx + ty + i * 8;
        d[(size_t)orow * DD + by + tx] = __float2bfloat16(tile[tx][ty + i * 8]);
    }
}

// ---------------------------------------------------------------------------
// LayerNorm
// ---------------------------------------------------------------------------
__device__ __forceinline__ float block_sum(float v) {
    __shared__ float sh[8];
    int lane = threadIdx.x & 31, w = threadIdx.x >> 5;
    #pragma unroll
    for (int o = 16; o; o >>= 1) v += __shfl_xor_sync(0xffffffffu, v, o);
    __syncthreads();
    if (lane == 0) sh[w] = v;
    __syncthreads();
    float t = 0.f;
    #pragma unroll
    for (int i = 0; i < 8; i++) t += sh[i];
    return t;
}

__global__ __launch_bounds__(256) void ln_kernel(
    const float* __restrict__ x, const float* __restrict__ w,
    const float* __restrict__ b, bf16* __restrict__ out)
{
    size_t row = blockIdx.x;
    int t = threadIdx.x;
    float4 v = ((const float4*)(x + row*DD))[t];
    float mu = block_sum(v.x + v.y + v.z + v.w) * (1.f/1024.f);
    float dx = v.x - mu, dy = v.y - mu, dz = v.z - mu, dw = v.w - mu;
    float var = block_sum(dx*dx + dy*dy + dz*dz + dw*dw) * (1.f/1024.f);
    float rs = rsqrtf(var + 1e-5f);
    float4 wv = ((const float4*)w)[t];
    float4 bv = ((const float4*)b)[t];
    bf162* o2 = (bf162*)(out + row*DD);
    o2[t*2+0] = __floats2bfloat162_rn(dx*rs*wv.x + bv.x, dy*rs*wv.y + bv.y);
    o2[t*2+1] = __floats2bfloat162_rn(dz*rs*wv.z + bv.z, dw*rs*wv.w + bv.w);
}

// ---------------------------------------------------------------------------
// RoPE
// ---------------------------------------------------------------------------
__global__ void rope_table_kernel() {
    int idx = blockIdx.x*256 + threadIdx.x;   // 65536 = 2048*32
    int m = idx >> 5, i = idx & 31;
    double e = (double)(2*i) / 64.0;
    float invf = (float)(1.0 / pow(10000.0, e));
    float ang = (float)m * invf;
    double a = (double)ang;
    g_ropeC[idx] = (float)cos(a);
    g_ropeS[idx] = (float)sin(a);
}

__global__ __launch_bounds__(256) void rope_bf16_kernel(
    bf16* __restrict__ Q, bf16* __restrict__ K)
{
    int idx = blockIdx.x*256 + threadIdx.x;   // NN*HH*16 = 2097152
    int n = idx >> 8;
    int r = idx & 255;
    int h = r >> 4;
    int i2 = (r & 15) << 1;
    int m = n & (MM - 1);
    float c0 = g_ropeC[m*32 + i2],     s0 = g_ropeS[m*32 + i2];
    float c1 = g_ropeC[m*32 + i2 + 1], s1 = g_ropeS[m*32 + i2 + 1];
    size_t base = (size_t)n*DD + h*DH;
    bf162* Qp = (bf162*)(Q + base);
    bf162* Kp = (bf162*)(K + base);
    int p = i2 >> 1;
    float2 qa = __bfloat1622float2(Qp[p]);
    float2 qb = __bfloat1622float2(Qp[p + 16]);
    Qp[p]      = __floats2bfloat162_rn(qa.x*c0 - qb.x*s0, qa.y*c1 - qb.y*s1);
    Qp[p + 16] = __floats2bfloat162_rn(qb.x*c0 + qa.x*s0, qb.y*c1 + qa.y*s1);
    float2 ka = __bfloat1622float2(Kp[p]);
    float2 kb = __bfloat1622float2(Kp[p + 16]);
    Kp[p]      = __floats2bfloat162_rn(ka.x*c0 - kb.x*s0, ka.y*c1 - kb.y*s1);
    Kp[p + 16] = __floats2bfloat162_rn(kb.x*c0 + ka.x*s0, kb.y*c1 + ka.y*s1);
}

// ---------------------------------------------------------------------------
// bf16 tensor-core flash attention (proven R7 path).
// ---------------------------------------------------------------------------
#define FAB_SMEM 49664

__global__ __launch_bounds__(256) void fa_bf16_kernel(
    const bf16* __restrict__ Q, const bf16* __restrict__ K,
    const bf16* __restrict__ V, const int* __restrict__ mask,
    bf16* __restrict__ O)
{
    extern __shared__ char fasm[];
    const uint32_t sQ = (uint32_t)__cvta_generic_to_shared(fasm);
    const uint32_t sK = sQ + 16384;
    const uint32_t sV = sQ + 32768;
    float* maskb = (float*)(fasm + 49152);

    const int tid = threadIdx.x, lane = tid & 31, wid = tid >> 5;
    const int m0 = blockIdx.x * 128;
    const int b = blockIdx.y >> 4, h = blockIdx.y & 15;

    {
        const bf16* Qg = Q + ((size_t)(b*MM + m0))*DD + h*DH;
        #pragma unroll
        for (int t = 0; t < 4; t++) {
            int j = tid + (t << 8);
            int r = j >> 3, c = j & 7;
            cp16(sQ + (((r << 6) + ((c ^ (r & 7)) << 3)) << 1),
                 Qg + (size_t)r*DD + (c << 3));
        }
        cp_commit();
    }

    auto issueKV = [&](int tkv, int bb) {
        size_t base = ((size_t)(b*MM + tkv*64))*DD + h*DH;
        #pragma unroll
        for (int t = 0; t < 2; t++) {
            int j = tid + (t << 8);
            int r = j >> 3, c = j & 7;
            uint32_t off = (((r << 6) + ((c ^ (r & 7)) << 3)) << 1) + bb*8192;
            cp16(sK + off, K + base + (size_t)r*DD + (c << 3));
            cp16(sV + off, V + base + (size_t)r*DD + (c << 3));
        }
        if (tid < 64)
            maskb[bb*64 + tid] = mask[b*MM + tkv*64 + tid] ? 0.f : -1e30f;
    };

    issueKV(0, 0);
    cp_commit();
    asm volatile("cp.async.wait_group 0;\n" ::: "memory");
    __syncthreads();

    uint32_t qf[4][4];
    {
        int row = (wid << 4) + (lane & 15);
        #pragma unroll
        for (int ks = 0; ks < 4; ks++) {
            int ch = 2*ks + (lane >> 4);
            ldsm4(qf[ks], sQ + (((row << 6) + ((ch ^ (row & 7)) << 3)) << 1));
        }
    }

    float o_acc[8][4];
    #pragma unroll
    for (int i = 0; i < 8; i++)
        #pragma unroll
        for (int j = 0; j < 4; j++) o_acc[i][j] = 0.f;
    float mrow[2] = {-1e30f, -1e30f}, lrow[2] = {0.f, 0.f};

    int buf = 0;
    for (int t = 0; t < MM/64; t++) {
        if (t + 1 < MM/64) { issueKV(t + 1, buf ^ 1); cp_commit(); }

        float s_acc[8][4];
        #pragma unroll
        for (int i = 0; i < 8; i++)
            #pragma unroll
            for (int j = 0; j < 4; j++) s_acc[i][j] = 0.f;

        const uint32_t kb = sK + buf*8192;
        #pragma unroll
        for (int ks = 0; ks < 4; ks++) {
            #pragma unroll
            for (int kvt = 0; kvt < 4; kvt++) {
                uint32_t kf[4];
                int row = (kvt << 4) + (lane & 15);
                int ch = 2*ks + (lane >> 4);
                ldsm4(kf, kb + (((row << 6) + ((ch ^ (row & 7)) << 3)) << 1));
                mma_bf16(s_acc[kvt*2+0], qf[ks], kf[0], kf[2]);
                mma_bf16(s_acc[kvt*2+1], qf[ks], kf[1], kf[3]);
            }
        }

        const float* mbuf = maskb + buf*64;
        float bias0[8], bias1[8];
        #pragma unroll
        for (int tl = 0; tl < 8; tl++) {
            bias0[tl] = mbuf[tl*8 + ((lane & 3) << 1)];
            bias1[tl] = mbuf[tl*8 + ((lane & 3) << 1) + 1];
        }
        #pragma unroll
        for (int hh = 0; hh < 2; hh++) {
            float mx = -1e30f;
            #pragma unroll
            for (int tl = 0; tl < 8; tl++) {
                float v0 = s_acc[tl][hh*2+0]*0.125f + bias0[tl];
                float v1 = s_acc[tl][hh*2+1]*0.125f + bias1[tl];
                s_acc[tl][hh*2+0] = v0; s_acc[tl][hh*2+1] = v1;
                mx = fmaxf(mx, fmaxf(v0, v1));
            }
            mx = fmaxf(mx, __shfl_xor_sync(0xffffffffu, mx, 1));
            mx = fmaxf(mx, __shfl_xor_sync(0xffffffffu, mx, 2));
            float mn = fmaxf(mrow[hh], mx);
            float corr = __expf(mrow[hh] - mn);
            mrow[hh] = mn;
            float ps = 0.f;
            #pragma unroll
            for (int tl = 0; tl < 8; tl++) {
                float p0 = __expf(s_acc[tl][hh*2+0] - mn);
                float p1 = __expf(s_acc[tl][hh*2+1] - mn);
                s_acc[tl][hh*2+0] = p0; s_acc[tl][hh*2+1] = p1;
                ps += p0 + p1;
            }
            ps += __shfl_xor_sync(0xffffffffu, ps, 1);
            ps += __shfl_xor_sync(0xffffffffu, ps, 2);
            lrow[hh] = lrow[hh]*corr + ps;
            #pragma unroll
            for (int tl = 0; tl < 8; tl++) {
                o_acc[tl][hh*2+0] *= corr;
                o_acc[tl][hh*2+1] *= corr;
            }
        }

        uint32_t ap[4][4];
        #pragma unroll
        for (int j = 0; j < 4; j++) {
            ap[j][0] = packbf(s_acc[2*j][0],   s_acc[2*j][1]);
            ap[j][1] = packbf(s_acc[2*j][2],   s_acc[2*j][3]);
            ap[j][2] = packbf(s_acc[2*j+1][0], s_acc[2*j+1][1]);
            ap[j][3] = packbf(s_acc[2*j+1][2], s_acc[2*j+1][3]);
        }

        const uint32_t vb = sV + buf*8192;
        #pragma unroll
        for (int j = 0; j < 4; j++) {
            #pragma unroll
            for (int nt = 0; nt < 4; nt++) {
                uint32_t vf[4];
                int krow = (j << 4) + (lane & 15);
                int ch = nt*2 + (lane >> 4);
                ldsm4t(vf, vb + (((krow << 6) + ((ch ^ (krow & 7)) << 3)) << 1));
                mma_bf16(o_acc[nt*2+0], ap[j], vf[0], vf[1]);
                mma_bf16(o_acc[nt*2+1], ap[j], vf[2], vf[3]);
            }
        }

        asm volatile("cp.async.wait_group 0;\n" ::: "memory");
        __syncthreads();
        buf ^= 1;
    }

    #pragma unroll
    for (int hh = 0; hh < 2; hh++) {
        float inv = 1.f / lrow[hh];
        int token = b*MM + m0 + (wid << 4) + (lane >> 2) + hh*8;
        size_t rowoff = (size_t)token*DD + h*DH + ((lane & 3) << 1);
        #pragma unroll
        for (int tl = 0; tl < 8; tl++) {
            *(bf162*)&O[rowoff + tl*8] =
                __floats2bfloat162_rn(o_acc[tl][hh*2+0]*inv, o_acc[tl][hh*2+1]*inv);
        }
    }
}

// ---------------------------------------------------------------------------
// Host launcher
// ---------------------------------------------------------------------------
extern "C" void kernel_launch(void* const* d_in, const int* in_sizes, int n_in,
                              void* d_out, int out_size)
{
    const float* x    = (const float*)d_in[0];
    const int*   mask = (const int*)  d_in[1];
    const float* ln1w = (const float*)d_in[2];
    const float* ln1b = (const float*)d_in[3];
    const float* ln2w = (const float*)d_in[4];
    const float* ln2b = (const float*)d_in[5];
    const float* Uq   = (const float*)d_in[6];
    const float* Uk   = (const float*)d_in[7];
    const float* Uv   = (const float*)d_in[8];
    const float* Vq   = (const float*)d_in[9];
    const float* Vk   = (const float*)d_in[10];
    const float* Vv   = (const float*)d_in[11];
    const float* bq   = (const float*)d_in[12];
    const float* bk   = (const float*)d_in[13];
    const float* bv   = (const float*)d_in[14];
    const float* Wo   = (const float*)d_in[15];
    const float* Wob  = (const float*)d_in[16];
    const float* U1   = (const float*)d_in[17];
    const float* V1   = (const float*)d_in[18];
    const float* b1   = (const float*)d_in[19];
    const float* U2   = (const float*)d_in[20];
    const float* V2   = (const float*)d_in[21];
    const float* b2   = (const float*)d_in[22];
    float* out = (float*)d_out;

    void* p;
    #define SYMB(var, sym) cudaGetSymbolAddress(&p, sym); bf16* var = (bf16*)p;
    SYMB(bXN,  g_bXN);   SYMB(bPqkv, g_bPqkv);
    SYMB(bQ,   g_bQ);    SYMB(bK,  g_bK);   SYMB(bV,  g_bV);
    SYMB(bAO,  g_bAO);   SYMB(bXN2,g_bXN2); SYMB(bP2, g_bP2);
    SYMB(bG,   g_bG);    SYMB(bT,  g_bT);
    SYMB(wUqkv,g_wUqkv);
    SYMB(wVq,  g_wVq);   SYMB(wVk, g_wVk);  SYMB(wVv, g_wVv);
    SYMB(wWoT, g_wWoT);  SYMB(wU1, g_wU1);  SYMB(wV1P,g_wV1P);
    SYMB(wU2,  g_wU2);   SYMB(wV2, g_wV2);
    #undef SYMB

    cudaFuncSetAttribute(fa_bf16_kernel,
        cudaFuncAttributeMaxDynamicSharedMemorySize, FAB_SMEM);
    cudaFuncSetAttribute(hgemm<false,false,false>,
        cudaFuncAttributeMaxDynamicSharedMemorySize, 65536);
    cudaFuncSetAttribute(hgemm<true,false,false>,
        cudaFuncAttributeMaxDynamicSharedMemorySize, 65536);
    cudaFuncSetAttribute(hgemm<true,true,true>,
        cudaFuncAttributeMaxDynamicSharedMemorySize, 65536);
    cudaFuncSetAttribute(hgemm_geglu,
        cudaFuncAttributeMaxDynamicSharedMemorySize, 65536);

    // [0] LN1 (needs only x)
    ln_kernel<<<NN, 256>>>(x, ln1w, ln1b, bXN);
    // [1-3] pack Uq|Uk|Uv -> [1024, 768]
    f2b_stride_kernel<<<(DD*RR/4)/256, 256>>>(Uq, wUqkv, RR, 3*RR, 0);
    f2b_stride_kernel<<<(DD*RR/4)/256, 256>>>(Uk, wUqkv, RR, 3*RR, RR);
    f2b_stride_kernel<<<(DD*RR/4)/256, 256>>>(Uv, wUqkv, RR, 3*RR, 2*RR);
    // [4] rope tables
    rope_table_kernel<<<256, 256>>>();
    // [5] merged rank projection  (ncu -s 5 profiles THIS launch)
    hgemm<false,false,false><<<dim3(3*RR/128, NN/128), 256, 65536>>>(
        bXN, wUqkv, nullptr, nullptr, bPqkv, 3*RR, DD, DD);

    // Remaining weight conversions
    #define CVT(src, dst, n) f2b_kernel<<<(n)/1024, 256>>>(src, dst)
    CVT(Vq, wVq, RR*DD);  CVT(Vk, wVk, RR*DD);  CVT(Vv, wVv, RR*DD);
    CVT(U1, wU1, DD*RR1); CVT(U2, wU2, FD*RR2); CVT(V2, wV2, RR2*DD);
    #undef CVT
    f2b_geglu_kernel<<<(RR1*2*FD/4)/256, 256>>>(V1, wV1P);
    transb_kernel<<<dim3(32,32), 256>>>(Wo, wWoT);

    // Expand + bias: [N,256]@[256,1024] -> bf16 Q/K/V (A strided in bPqkv)
    hgemm<true,false,false><<<dim3(DD/128, NN/128), 256, 65536>>>(
        bPqkv + 0,    wVq, bq, nullptr, bQ, DD, RR, 3*RR);
    hgemm<true,false,false><<<dim3(DD/128, NN/128), 256, 65536>>>(
        bPqkv + RR,   wVk, bk, nullptr, bK, DD, RR, 3*RR);
    hgemm<true,false,false><<<dim3(DD/128, NN/128), 256, 65536>>>(
        bPqkv + 2*RR, wVv, bv, nullptr, bV, DD, RR, 3*RR);

    // RoPE in place on bf16 Q, K
    rope_bf16_kernel<<<(NN*HH*16)/256, 256>>>(bQ, bK);

    // bf16 flash attention -> bAO
    fa_bf16_kernel<<<dim3(MM/128, BB*HH), 256, FAB_SMEM>>>(bQ, bK, bV, mask, bAO);

    // Out-proj + bias + residual(x) -> d_out fp32
    hgemm<true,true,true><<<dim3(DD/128, NN/128), 256, 65536>>>(
        bAO, wWoT, Wob, x, out, DD, DD, DD);

    // LN2 -> bf16
    ln_kernel<<<NN, 256>>>(out, ln2w, ln2b, bXN2);

    // FFN rank path: P2 = XN2 @ U1 ; G = geglu(P2 @ V1P + b1) fused ; T = G @ U2
    hgemm<false,false,false><<<dim3(RR1/128, NN/128), 256, 65536>>>(
        bXN2, wU1, nullptr, nullptr, bP2, RR1, DD, DD);
    hgemm_geglu<<<dim3((2*FD)/128, NN/128), 256, 65536>>>(
        bP2, wV1P, b1, bG, 2*FD, RR1, RR1);
    hgemm<false,false,false><<<dim3(RR2/128, NN/128), 256, 65536>>>(
        bG, wU2, nullptr, nullptr, bT, RR2, FD, FD);

    // Final: out = out(residual) + T @ V2 + b2 (in-place residual safe:
    // each element read then written by the same thread)
    hgemm<true,true,true><<<dim3(DD/128, NN/128), 256, 65536>>>(
        bT, wV2, b2, out, out, DD, RR2, RR2);
}